// round 16
// baseline (speedup 1.0000x reference)
#include <cuda_runtime.h>
#include <cuda_bf16.h>
#include <cstdint>
#include <cstddef>

#define LAT 128
#define NNODES 50000
#define NEDGES 400000
#define EPSV 1e-5f

// fp32: agg | Y12 [N,256] | Ye [E,128]
__device__ float g_fbuf[(size_t)(3 * NNODES + NEDGES) * LAT];
__device__ __align__(16) __nv_bfloat16 g_hpl[(size_t)4 * NNODES * LAT];
__device__ __align__(16) __nv_bfloat16 g_epl[(size_t)4 * NEDGES * LAT];
__device__ __align__(16) __nv_bfloat16 g_planes[294912];

__device__ __forceinline__ uint32_t smem_u32(const void* p) {
    uint32_t a;
    asm("{ .reg .u64 t; cvta.to.shared.u64 t, %1; cvt.u32.u64 %0, t; }" : "=r"(a) : "l"(p));
    return a;
}
__device__ __forceinline__ void ldsm4(uint32_t addr, uint32_t* r) {
    asm volatile("ldmatrix.sync.aligned.m8n8.x4.shared.b16 {%0,%1,%2,%3}, [%4];"
                 : "=r"(r[0]), "=r"(r[1]), "=r"(r[2]), "=r"(r[3]) : "r"(addr));
}
__device__ __forceinline__ void mma_bf16(float* d, const uint32_t* a, const uint32_t* b) {
    asm volatile("mma.sync.aligned.m16n8k16.row.col.f32.bf16.bf16.f32 "
                 "{%0,%1,%2,%3}, {%4,%5,%6,%7}, {%8,%9}, {%0,%1,%2,%3};"
                 : "+f"(d[0]), "+f"(d[1]), "+f"(d[2]), "+f"(d[3])
                 : "r"(a[0]), "r"(a[1]), "r"(a[2]), "r"(a[3]), "r"(b[0]), "r"(b[1]));
}
__device__ __forceinline__ void cpa16(uint32_t saddr, const void* g) {
    asm volatile("cp.async.cg.shared.global [%0], [%1], 16;"
                 :: "r"(saddr), "l"(g) : "memory");
}
#define CPA_COMMIT() asm volatile("cp.async.commit_group;" ::: "memory")
#define CPA_WAIT(N)  asm volatile("cp.async.wait_group %0;" :: "n"(N) : "memory")
__device__ __forceinline__ void red2(float* addr, float v0, float v1) {
    asm volatile("red.global.add.v2.f32 [%0], {%1, %2};"
                 :: "l"(addr), "f"(v0), "f"(v1) : "memory");
}
__device__ __forceinline__ uint32_t swz(uint32_t bo) { return bo ^ ((bo >> 3) & 0x70); }
__device__ __forceinline__ void split_pair(float a, float b, uint32_t& hi, uint32_t& lo) {
    __nv_bfloat16 ah = __float2bfloat16(a), bh = __float2bfloat16(b);
    __nv_bfloat162 hp; hp.x = ah; hp.y = bh;
    __nv_bfloat162 lp;
    lp.x = __float2bfloat16(a - __bfloat162float(ah));
    lp.y = __float2bfloat16(b - __bfloat162float(bh));
    hi = *reinterpret_cast<uint32_t*>(&hp);
    lo = *reinterpret_cast<uint32_t*>(&lp);
}
__device__ __forceinline__ float recon(uint32_t packed, int half) {
    __nv_bfloat162 v = *reinterpret_cast<__nv_bfloat162*>(&packed);
    return half ? __bfloat162float(v.y) : __bfloat162float(v.x);
}

// ============================================================================
// gemm_y12 (pre-loop only): Y12[r,0:128]=h@W1a ; Y12[r,128:256]=h@W1b
// ============================================================================
#define Y_A_HI 0
#define Y_A_LO 32768
#define Y_B_HI 65536
#define Y_B_LO 81920
#define SMEM_Y 98304

__global__ __launch_bounds__(256, 2) void gemm_y12(
    const __nv_bfloat16* __restrict__ aHi, const __nv_bfloat16* __restrict__ aLo,
    const __nv_bfloat16* __restrict__ bHi, const __nv_bfloat16* __restrict__ bLo,
    float* __restrict__ out, int nRows)
{
    extern __shared__ char smp[];
    const uint32_t sb = smem_u32(smp);
    const int tid = threadIdx.x;
    const int wid = tid >> 5, lane = tid & 31;
    const int mwarp = wid & 3, nwarp = wid >> 2;
    const int blockRow = blockIdx.x * 128;

#pragma unroll
    for (int p = 0; p < 8; p++) {
        int idx = tid + 256 * p;
        int row = idx >> 4, q = idx & 15;
        int c2 = q >> 3, qq = q & 7;
        int rc = min(blockRow + row, nRows - 1);
        size_t ga = (size_t)rc * 128 + q * 8;
        uint32_t sw = (uint32_t)(c2 * 16384) + swz((uint32_t)(row * 128 + qq * 16));
        cpa16(sb + Y_A_HI + sw, aHi + ga);
        cpa16(sb + Y_A_LO + sw, aLo + ga);
    }
    auto fillB = [&](int m) {
#pragma unroll
        for (int p = 0; p < 4; p++) {
            int idx = tid + 256 * p;
            int row = idx >> 3, qq = idx & 7;
            size_t gb = (size_t)row * 384 + m * 64 + qq * 8;
            uint32_t sw = swz((uint32_t)(row * 128 + qq * 16));
            cpa16(sb + Y_B_HI + sw, bHi + gb);
            cpa16(sb + Y_B_LO + sw, bLo + gb);
        }
    };
    fillB(0);
    CPA_COMMIT();

    const int lrow = lane & 7, lg = lane >> 3;
    const uint32_t xm = (uint32_t)lrow << 4;
    const int a_row0 = mwarp * 32 + lrow + 8 * (lg & 1);
    const int a_kx = lg >> 1;
    const int b_row0 = nwarp * 64 + lrow + 8 * (lg >> 1);
    const int b_kx = lg & 1;

    for (int blk = 0; blk < 2; blk++) {
        float c[2][8][4];
#pragma unroll
        for (int mt = 0; mt < 2; mt++)
#pragma unroll
            for (int i = 0; i < 8; i++)
#pragma unroll
                for (int j = 0; j < 4; j++) c[mt][i][j] = 0.f;

        for (int c2 = 0; c2 < 2; c2++) {
            CPA_WAIT(0);
            __syncthreads();
            const uint32_t abH = sb + Y_A_HI + c2 * 16384;
            const uint32_t abL = sb + Y_A_LO + c2 * 16384;
#pragma unroll
            for (int ks = 0; ks < 4; ks++) {
                const uint32_t kcA = (uint32_t)((ks * 2 + a_kx) * 16) ^ xm;
                const uint32_t kcB = (uint32_t)((ks * 2 + b_kx) * 16) ^ xm;
                uint32_t ah[2][4], al[2][4];
#pragma unroll
                for (int mt = 0; mt < 2; mt++) {
                    uint32_t ro = (uint32_t)((a_row0 + mt * 16) * 128);
                    ldsm4(abH + ro + kcA, ah[mt]);
                    ldsm4(abL + ro + kcA, al[mt]);
                }
#pragma unroll
                for (int g = 0; g < 4; g++) {
                    uint32_t bh[4], bl[4];
                    uint32_t ro = (uint32_t)((b_row0 + g * 16) * 128);
                    ldsm4(sb + Y_B_HI + ro + kcB, bh);
                    ldsm4(sb + Y_B_LO + ro + kcB, bl);
#pragma unroll
                    for (int mt = 0; mt < 2; mt++)
#pragma unroll
                        for (int hf = 0; hf < 2; hf++) {
                            float* cc = c[mt][g * 2 + hf];
                            mma_bf16(cc, ah[mt], &bh[hf * 2]);
                            mma_bf16(cc, ah[mt], &bl[hf * 2]);
                            mma_bf16(cc, al[mt], &bh[hf * 2]);
                        }
                }
            }
            __syncthreads();
            int m = blk * 2 + c2;
            if (m < 3) { fillB(m + 1); CPA_COMMIT(); }
        }

#pragma unroll
        for (int mt = 0; mt < 2; mt++)
#pragma unroll
            for (int e = 0; e < 2; e++) {
                int row = mwarp * 32 + mt * 16 + (lane >> 2) + 8 * e;
                int gr = blockRow + row;
                if (gr >= nRows) continue;
#pragma unroll
                for (int idx = 0; idx < 8; idx++) {
                    int col = nwarp * 64 + (idx >> 1) * 16 + (idx & 1) * 8 + 2 * (lane & 3);
                    float2 o;
                    o.x = c[mt][idx][2 * e];
                    o.y = c[mt][idx][2 * e + 1];
                    *(float2*)&out[(size_t)gr * 256 + blk * 128 + col] = o;
                }
            }
    }
}

// ============================================================================
// edge_fused: MSG scatter [+ EDGE update + Ye tail when doTail]
// ============================================================================
#define E_H_HI 0
#define E_H_LO 32768
#define E_W2   65536
#define E_IDX  98304
#define E_B2   99328
#define E_G    99840
#define E_BE   100352
#define E_B1   100864
#define E_LN   101376
#define SMEM_E 103424

__global__ __launch_bounds__(256, 2) void edge_fused(
    const float* __restrict__ Y12, float* __restrict__ Ye,
    const int* __restrict__ dst, const int* __restrict__ src,
    const __nv_bfloat16* __restrict__ W2hi, const __nv_bfloat16* __restrict__ W2lo,
    const float* __restrict__ B2, const float* __restrict__ G,
    const float* __restrict__ BE,
    const __nv_bfloat16* __restrict__ W1hi, const __nv_bfloat16* __restrict__ W1lo,
    const float* __restrict__ B1,
    const __nv_bfloat16* __restrict__ resHi, const __nv_bfloat16* __restrict__ resLo,
    __nv_bfloat16* __restrict__ outHi, __nv_bfloat16* __restrict__ outLo,
    float* __restrict__ aggF, int doTail, int nRows)
{
    extern __shared__ char smp[];
    const uint32_t sb = smem_u32(smp);
    const int tid = threadIdx.x;
    const int wid = tid >> 5, lane = tid & 31;
    const int mwarp = wid & 3, nwarp = wid >> 2;
    const int blockRow = blockIdx.x * 128;

    int* idxs = (int*)(smp + E_IDX);
    float* b2s = (float*)(smp + E_B2);
    float* Gs  = (float*)(smp + E_G);
    float* BEs = (float*)(smp + E_BE);
    float* b1s = (float*)(smp + E_B1);
    float* lnb = (float*)(smp + E_LN);

    if (tid < 128) {
        idxs[tid] = dst[min(blockRow + tid, nRows - 1)];
        b2s[tid] = B2[tid]; Gs[tid] = G[tid]; BEs[tid] = BE[tid];
        b1s[tid] = B1[tid];
    } else {
        idxs[tid] = src[min(blockRow + tid - 128, nRows - 1)];
    }
    __syncthreads();

    auto fillW2 = [&](int chunk) {
#pragma unroll
        for (int p = 0; p < 4; p++) {
            int idx = tid + 256 * p;
            int row = idx >> 3, qq = idx & 7;
            size_t go = (size_t)row * 128 + chunk * 64 + qq * 8;
            uint32_t sw = swz((uint32_t)(row * 128 + qq * 16));
            cpa16(sb + E_W2 + sw, W2hi + go);
            cpa16(sb + E_W2 + 16384 + sw, W2lo + go);
        }
    };
    auto fillW1c = [&](int chunk) {
#pragma unroll
        for (int p = 0; p < 4; p++) {
            int idx = tid + 256 * p;
            int row = idx >> 3, qq = idx & 7;
            size_t go = (size_t)row * 384 + 256 + chunk * 64 + qq * 8;
            uint32_t sw = swz((uint32_t)(row * 128 + qq * 16));
            cpa16(sb + E_W2 + sw, W1hi + go);
            cpa16(sb + E_W2 + 16384 + sw, W1lo + go);
        }
    };
    fillW2(0); CPA_COMMIT();

    const int lrow = lane & 7, lg = lane >> 3;
    const uint32_t xm = (uint32_t)lrow << 4;
    const int a_row0 = mwarp * 32 + lrow + 8 * (lg & 1);
    const int a_kx = lg >> 1;
    const int b_row0 = nwarp * 64 + lrow + 8 * (lg >> 1);
    const int b_kx = lg & 1;

    const int nPh = doTail ? 2 : 1;
    for (int ph = 0; ph < nPh; ph++) {
        const bool MSG = (ph == 0);
#pragma unroll 4
        for (int p = 0; p < 16; p++) {
            int idx = tid + 256 * p;
            int row = idx >> 5, qf = idx & 31;
            int col = qf * 4;
            int gr = min(blockRow + row, nRows - 1);
            int riA = MSG ? idxs[row] : idxs[128 + row];
            int riB = MSG ? idxs[128 + row] : idxs[row];
            float4 a = *(const float4*)&Y12[(size_t)riA * 256 + col];
            float4 b = *(const float4*)&Y12[(size_t)riB * 256 + 128 + col];
            float4 e4 = *(const float4*)&Ye[(size_t)gr * 128 + col];
            float v0 = fmaxf(a.x + b.x + e4.x, 0.f);
            float v1 = fmaxf(a.y + b.y + e4.y, 0.f);
            float v2 = fmaxf(a.z + b.z + e4.z, 0.f);
            float v3 = fmaxf(a.w + b.w + e4.w, 0.f);
            uint32_t h0, h1, l0, l1;
            split_pair(v0, v1, h0, l0);
            split_pair(v2, v3, h1, l1);
            uint32_t off = (uint32_t)((col >> 6) * 16384) +
                           swz((uint32_t)(row * 128 + (col & 63) * 2));
            *(uint2*)(smp + E_H_HI + off) = make_uint2(h0, h1);
            *(uint2*)(smp + E_H_LO + off) = make_uint2(l0, l1);
        }

        float c[2][8][4];
#pragma unroll
        for (int mt = 0; mt < 2; mt++)
#pragma unroll
            for (int i = 0; i < 8; i++)
#pragma unroll
                for (int j = 0; j < 4; j++) c[mt][i][j] = 0.f;

        for (int c2 = 0; c2 < 2; c2++) {
            CPA_WAIT(0);
            __syncthreads();
            const uint32_t abH = sb + E_H_HI + c2 * 16384;
            const uint32_t abL = sb + E_H_LO + c2 * 16384;
#pragma unroll
            for (int ks = 0; ks < 4; ks++) {
                const uint32_t kcA = (uint32_t)((ks * 2 + a_kx) * 16) ^ xm;
                const uint32_t kcB = (uint32_t)((ks * 2 + b_kx) * 16) ^ xm;
                uint32_t ah[2][4], al[2][4];
#pragma unroll
                for (int mt = 0; mt < 2; mt++) {
                    uint32_t ro = (uint32_t)((a_row0 + mt * 16) * 128);
                    ldsm4(abH + ro + kcA, ah[mt]);
                    ldsm4(abL + ro + kcA, al[mt]);
                }
#pragma unroll
                for (int g = 0; g < 4; g++) {
                    uint32_t bh[4], bl[4];
                    uint32_t ro = (uint32_t)((b_row0 + g * 16) * 128);
                    ldsm4(sb + E_W2 + ro + kcB, bh);
                    ldsm4(sb + E_W2 + 16384 + ro + kcB, bl);
#pragma unroll
                    for (int mt = 0; mt < 2; mt++)
#pragma unroll
                        for (int hf = 0; hf < 2; hf++) {
                            float* cc = c[mt][g * 2 + hf];
                            mma_bf16(cc, ah[mt], &bh[hf * 2]);
                            mma_bf16(cc, ah[mt], &bl[hf * 2]);
                            mma_bf16(cc, al[mt], &bh[hf * 2]);
                        }
                }
            }
            __syncthreads();
            if (c2 == 0) { fillW2(1); CPA_COMMIT(); }
            else if (MSG && doTail) { fillW2(0); CPA_COMMIT(); }
            else if (!MSG) { fillW1c(0); CPA_COMMIT(); }
        }

#pragma unroll
        for (int mt = 0; mt < 2; mt++)
#pragma unroll
            for (int idx = 0; idx < 8; idx++) {
                int col = nwarp * 64 + (idx >> 1) * 16 + (idx & 1) * 8 + 2 * (lane & 3);
#pragma unroll
                for (int j = 0; j < 4; j++)
                    c[mt][idx][j] = fmaxf(c[mt][idx][j] + b2s[col + (j & 1)], 0.f);
            }

#pragma unroll
        for (int mt = 0; mt < 2; mt++)
#pragma unroll
            for (int e = 0; e < 2; e++) {
                float s = 0.f;
#pragma unroll
                for (int idx = 0; idx < 8; idx++)
                    s += c[mt][idx][2 * e] + c[mt][idx][2 * e + 1];
                s += __shfl_xor_sync(0xffffffffu, s, 1);
                s += __shfl_xor_sync(0xffffffffu, s, 2);
                if ((lane & 3) == 0) {
                    int row = mwarp * 32 + mt * 16 + (lane >> 2) + 8 * e;
                    lnb[row * 2 + nwarp] = s;
                }
            }
        __syncthreads();
        float mu[2][2], rs[2][2];
#pragma unroll
        for (int mt = 0; mt < 2; mt++)
#pragma unroll
            for (int e = 0; e < 2; e++) {
                int row = mwarp * 32 + mt * 16 + (lane >> 2) + 8 * e;
                mu[mt][e] = (lnb[row * 2] + lnb[row * 2 + 1]) * (1.0f / 128.0f);
                float sq = 0.f;
#pragma unroll
                for (int idx = 0; idx < 8; idx++) {
                    float d0 = c[mt][idx][2 * e] - mu[mt][e];
                    float d1 = c[mt][idx][2 * e + 1] - mu[mt][e];
                    sq = fmaf(d0, d0, sq);
                    sq = fmaf(d1, d1, sq);
                }
                sq += __shfl_xor_sync(0xffffffffu, sq, 1);
                sq += __shfl_xor_sync(0xffffffffu, sq, 2);
                if ((lane & 3) == 0) lnb[256 + row * 2 + nwarp] = sq;
            }
        __syncthreads();
#pragma unroll
        for (int mt = 0; mt < 2; mt++)
#pragma unroll
            for (int e = 0; e < 2; e++) {
                int row = mwarp * 32 + mt * 16 + (lane >> 2) + 8 * e;
                rs[mt][e] = rsqrtf((lnb[256 + row * 2] + lnb[256 + row * 2 + 1]) *
                                       (1.0f / 128.0f) + EPSV);
            }

#pragma unroll
        for (int mt = 0; mt < 2; mt++)
#pragma unroll
            for (int e = 0; e < 2; e++) {
                int row = mwarp * 32 + mt * 16 + (lane >> 2) + 8 * e;
                int gr = blockRow + row;
                if (gr >= nRows) continue;
                float m = mu[mt][e], q = rs[mt][e];
                if (MSG) {
                    const int drow = idxs[row];
                    float* op = aggF + (size_t)drow * LAT;
#pragma unroll
                    for (int idx = 0; idx < 8; idx++) {
                        int col = nwarp * 64 + (idx >> 1) * 16 + (idx & 1) * 8 + 2 * (lane & 3);
                        float v0 = (c[mt][idx][2 * e]     - m) * q * Gs[col]     + BEs[col];
                        float v1 = (c[mt][idx][2 * e + 1] - m) * q * Gs[col + 1] + BEs[col + 1];
                        red2(&op[col], v0, v1);
                    }
                } else {
#pragma unroll
                    for (int idx = 0; idx < 8; idx++) {
                        int col = nwarp * 64 + (idx >> 1) * 16 + (idx & 1) * 8 + 2 * (lane & 3);
                        float v0 = (c[mt][idx][2 * e]     - m) * q * Gs[col]     + BEs[col];
                        float v1 = (c[mt][idx][2 * e + 1] - m) * q * Gs[col + 1] + BEs[col + 1];
                        uint32_t rh = *(const uint32_t*)&resHi[(size_t)gr * LAT + col];
                        uint32_t rl = *(const uint32_t*)&resLo[(size_t)gr * LAT + col];
                        v0 += recon(rh, 0) + recon(rl, 0);
                        v1 += recon(rh, 1) + recon(rl, 1);
                        uint32_t hi, lo;
                        split_pair(v0, v1, hi, lo);
                        *(uint32_t*)&outHi[(size_t)gr * LAT + col] = hi;
                        *(uint32_t*)&outLo[(size_t)gr * LAT + col] = lo;
                        uint32_t off = (uint32_t)((col >> 6) * 16384) +
                                       swz((uint32_t)(row * 128 + (col & 63) * 2));
                        *(uint32_t*)(smp + E_H_HI + off) = hi;
                        *(uint32_t*)(smp + E_H_LO + off) = lo;
                    }
                }
            }
        __syncthreads();
    }

    if (doTail) {
        float c[2][8][4];
#pragma unroll
        for (int mt = 0; mt < 2; mt++)
#pragma unroll
            for (int i = 0; i < 8; i++)
#pragma unroll
                for (int j = 0; j < 4; j++) c[mt][i][j] = 0.f;

        for (int k2 = 0; k2 < 2; k2++) {
            CPA_WAIT(0);
            __syncthreads();
            const uint32_t abH = sb + E_H_HI + k2 * 16384;
            const uint32_t abL = sb + E_H_LO + k2 * 16384;
#pragma unroll
            for (int ks = 0; ks < 4; ks++) {
                const uint32_t kcA = (uint32_t)((ks * 2 + a_kx) * 16) ^ xm;
                const uint32_t kcB = (uint32_t)((ks * 2 + b_kx) * 16) ^ xm;
                uint32_t ah[2][4], al[2][4];
#pragma unroll
                for (int mt = 0; mt < 2; mt++) {
                    uint32_t ro = (uint32_t)((a_row0 + mt * 16) * 128);
                    ldsm4(abH + ro + kcA, ah[mt]);
                    ldsm4(abL + ro + kcA, al[mt]);
                }
#pragma unroll
                for (int g = 0; g < 4; g++) {
                    uint32_t bh[4], bl[4];
                    uint32_t ro = (uint32_t)((b_row0 + g * 16) * 128);
                    ldsm4(sb + E_W2 + ro + kcB, bh);
                    ldsm4(sb + E_W2 + 16384 + ro + kcB, bl);
#pragma unroll
                    for (int mt = 0; mt < 2; mt++)
#pragma unroll
                        for (int hf = 0; hf < 2; hf++) {
                            float* cc = c[mt][g * 2 + hf];
                            mma_bf16(cc, ah[mt], &bh[hf * 2]);
                            mma_bf16(cc, ah[mt], &bl[hf * 2]);
                            mma_bf16(cc, al[mt], &bh[hf * 2]);
                        }
                }
            }
            __syncthreads();
            if (k2 == 0) { fillW1c(1); CPA_COMMIT(); }
        }
#pragma unroll
        for (int mt = 0; mt < 2; mt++)
#pragma unroll
            for (int e = 0; e < 2; e++) {
                int row = mwarp * 32 + mt * 16 + (lane >> 2) + 8 * e;
                int gr = blockRow + row;
                if (gr >= nRows) continue;
#pragma unroll
                for (int idx = 0; idx < 8; idx++) {
                    int col = nwarp * 64 + (idx >> 1) * 16 + (idx & 1) * 8 + 2 * (lane & 3);
                    float2 o;
                    o.x = c[mt][idx][2 * e] + b1s[col];
                    o.y = c[mt][idx][2 * e + 1] + b1s[col + 1];
                    *(float2*)&Ye[(size_t)gr * 128 + col] = o;
                }
            }
    }
}

// ============================================================================
// encode_mlp: SIMT layer1 -> layer2 -> LN -> planes [+Ye tail]
// ============================================================================
#define N_H_HI 0
#define N_H_LO 32768
#define N_W2   65536
#define N_B1   98304
#define N_B2   98816
#define N_G    99328
#define N_BE   99840
#define N_LN   100352
#define N_W1R  102400
#define N_EB1  104448
#define SMEM_N 104960

__global__ __launch_bounds__(256, 2) void encode_mlp(
    const float* __restrict__ raw, const float* __restrict__ W1raw, int kreal,
    const float* __restrict__ B1,
    const __nv_bfloat16* __restrict__ W2hi, const __nv_bfloat16* __restrict__ W2lo,
    const float* __restrict__ B2,
    const float* __restrict__ G, const float* __restrict__ BE,
    const __nv_bfloat16* __restrict__ eW1hi, const __nv_bfloat16* __restrict__ eW1lo,
    const float* __restrict__ eB1, float* __restrict__ Ye, int doYe,
    __nv_bfloat16* __restrict__ outHi, __nv_bfloat16* __restrict__ outLo, int nRows)
{
    extern __shared__ char smp[];
    const uint32_t sb = smem_u32(smp);
    const int tid = threadIdx.x;
    const int wid = tid >> 5, lane = tid & 31;
    const int mwarp = wid & 3, nwarp = wid >> 2;
    const int blockRow = blockIdx.x * 128;

    float* b1s = (float*)(smp + N_B1);
    float* b2s = (float*)(smp + N_B2);
    float* Gs  = (float*)(smp + N_G);
    float* BEs = (float*)(smp + N_BE);
    float* lnb = (float*)(smp + N_LN);
    float* w1r = (float*)(smp + N_W1R);
    float* eb1 = (float*)(smp + N_EB1);

    if (tid < 128) {
        b1s[tid] = B1[tid]; b2s[tid] = B2[tid];
        Gs[tid] = G[tid];   BEs[tid] = BE[tid];
        if (doYe) eb1[tid] = eB1[tid];
    }
    for (int i = tid; i < kreal * 128; i += 256) w1r[i] = W1raw[i];
    __syncthreads();

    auto fillW2 = [&](int chunk) {
#pragma unroll
        for (int p = 0; p < 4; p++) {
            int idx = tid + 256 * p;
            int row = idx >> 3, qq = idx & 7;
            size_t go = (size_t)row * 128 + chunk * 64 + qq * 8;
            uint32_t sw = swz((uint32_t)(row * 128 + qq * 16));
            cpa16(sb + N_W2 + sw, W2hi + go);
            cpa16(sb + N_W2 + 16384 + sw, W2lo + go);
        }
    };
    auto fillW1c = [&](int chunk) {
#pragma unroll
        for (int p = 0; p < 4; p++) {
            int idx = tid + 256 * p;
            int row = idx >> 3, qq = idx & 7;
            size_t go = (size_t)row * 384 + 256 + chunk * 64 + qq * 8;
            uint32_t sw = swz((uint32_t)(row * 128 + qq * 16));
            cpa16(sb + N_W2 + sw, eW1hi + go);
            cpa16(sb + N_W2 + 16384 + sw, eW1lo + go);
        }
    };
    fillW2(0); CPA_COMMIT();

#pragma unroll 4
    for (int p = 0; p < 16; p++) {
        int idx = tid + 256 * p;
        int row = idx >> 5, qf = idx & 31;
        int col = qf * 4;
        int rc = min(blockRow + row, nRows - 1);
        float xv[4];
#pragma unroll
        for (int k = 0; k < 4; k++)
            xv[k] = (k < kreal) ? raw[(size_t)rc * kreal + k] : 0.f;
        float v[4];
#pragma unroll
        for (int j = 0; j < 4; j++) {
            float acc = b1s[col + j];
            for (int k = 0; k < kreal; k++)
                acc = fmaf(xv[k], w1r[k * 128 + col + j], acc);
            v[j] = fmaxf(acc, 0.f);
        }
        uint32_t h0, h1, l0, l1;
        split_pair(v[0], v[1], h0, l0);
        split_pair(v[2], v[3], h1, l1);
        uint32_t off = (uint32_t)((col >> 6) * 16384) +
                       swz((uint32_t)(row * 128 + (col & 63) * 2));
        *(uint2*)(smp + N_H_HI + off) = make_uint2(h0, h1);
        *(uint2*)(smp + N_H_LO + off) = make_uint2(l0, l1);
    }

    const int lrow = lane & 7, lg = lane >> 3;
    const uint32_t xm = (uint32_t)lrow << 4;
    const int a_row0 = mwarp * 32 + lrow + 8 * (lg & 1);
    const int a_kx = lg >> 1;
    const int b_row0 = nwarp * 64 + lrow + 8 * (lg >> 1);
    const int b_kx = lg & 1;

    float c[2][8][4];
#pragma unroll
    for (int mt = 0; mt < 2; mt++)
#pragma unroll
        for (int i = 0; i < 8; i++)
#pragma unroll
            for (int j = 0; j < 4; j++) c[mt][i][j] = 0.f;

    for (int c2 = 0; c2 < 2; c2++) {
        CPA_WAIT(0);
        __syncthreads();
        const uint32_t abH = sb + N_H_HI + c2 * 16384;
        const uint32_t abL = sb + N_H_LO + c2 * 16384;
#pragma unroll
        for (int ks = 0; ks < 4; ks++) {
            const uint32_t kcA = (uint32_t)((ks * 2 + a_kx) * 16) ^ xm;
            const uint32_t kcB = (uint32_t)((ks * 2 + b_kx) * 16) ^ xm;
            uint32_t ah[2][4], al[2][4];
#pragma unroll
            for (int mt = 0; mt < 2; mt++) {
                uint32_t ro = (uint32_t)((a_row0 + mt * 16) * 128);
                ldsm4(abH + ro + kcA, ah[mt]);
                ldsm4(abL + ro + kcA, al[mt]);
            }
#pragma unroll
            for (int g = 0; g < 4; g++) {
                uint32_t bh[4], bl[4];
                uint32_t ro = (uint32_t)((b_row0 + g * 16) * 128);
                ldsm4(sb + N_W2 + ro + kcB, bh);
                ldsm4(sb + N_W2 + 16384 + ro + kcB, bl);
#pragma unroll
                for (int mt = 0; mt < 2; mt++)
#pragma unroll
                    for (int hf = 0; hf < 2; hf++) {
                        float* cc = c[mt][g * 2 + hf];
                        mma_bf16(cc, ah[mt], &bh[hf * 2]);
                        mma_bf16(cc, ah[mt], &bl[hf * 2]);
                        mma_bf16(cc, al[mt], &bh[hf * 2]);
                    }
            }
        }
        __syncthreads();
        if (c2 == 0) { fillW2(1); CPA_COMMIT(); }
        else if (doYe) { fillW1c(0); CPA_COMMIT(); }
    }

#pragma unroll
    for (int mt = 0; mt < 2; mt++)
#pragma unroll
        for (int idx = 0; idx < 8; idx++) {
            int col = nwarp * 64 + (idx >> 1) * 16 + (idx & 1) * 8 + 2 * (lane & 3);
#pragma unroll
            for (int j = 0; j < 4; j++)
                c[mt][idx][j] = fmaxf(c[mt][idx][j] + b2s[col + (j & 1)], 0.f);
        }
#pragma unroll
    for (int mt = 0; mt < 2; mt++)
#pragma unroll
        for (int e = 0; e < 2; e++) {
            float s = 0.f;
#pragma unroll
            for (int idx = 0; idx < 8; idx++)
                s += c[mt][idx][2 * e] + c[mt][idx][2 * e + 1];
            s += __shfl_xor_sync(0xffffffffu, s, 1);
            s += __shfl_xor_sync(0xffffffffu, s, 2);
            if ((lane & 3) == 0) {
                int row = mwarp * 32 + mt * 16 + (lane >> 2) + 8 * e;
                lnb[row * 2 + nwarp] = s;
            }
        }
    __syncthreads();
    float mu[2][2], rs[2][2];
#pragma unroll
    for (int mt = 0; mt < 2; mt++)
#pragma unroll
        for (int e = 0; e < 2; e++) {
            int row = mwarp * 32 + mt * 16 + (lane >> 2) + 8 * e;
            mu[mt][e] = (lnb[row * 2] + lnb[row * 2 + 1]) * (1.0f / 128.0f);
            float sq = 0.f;
#pragma unroll
            for (int idx = 0; idx < 8; idx++) {
                float d0 = c[mt][idx][2 * e] - mu[mt][e];
                float d1 = c[mt][idx][2 * e + 1] - mu[mt][e];
                sq = fmaf(d0, d0, sq);
                sq = fmaf(d1, d1, sq);
            }
            sq += __shfl_xor_sync(0xffffffffu, sq, 1);
            sq += __shfl_xor_sync(0xffffffffu, sq, 2);
            if ((lane & 3) == 0) lnb[256 + row * 2 + nwarp] = sq;
        }
    __syncthreads();
#pragma unroll
    for (int mt = 0; mt < 2; mt++)
#pragma unroll
        for (int e = 0; e < 2; e++) {
            int row = mwarp * 32 + mt * 16 + (lane >> 2) + 8 * e;
            rs[mt][e] = rsqrtf((lnb[256 + row * 2] + lnb[256 + row * 2 + 1]) *
                                   (1.0f / 128.0f) + EPSV);
        }
#pragma unroll
    for (int mt = 0; mt < 2; mt++)
#pragma unroll
        for (int e = 0; e < 2; e++) {
            int row = mwarp * 32 + mt * 16 + (lane >> 2) + 8 * e;
            int gr = blockRow + row;
            if (gr >= nRows) continue;
            float m = mu[mt][e], q = rs[mt][e];
#pragma unroll
            for (int idx = 0; idx < 8; idx++) {
                int col = nwarp * 64 + (idx >> 1) * 16 + (idx & 1) * 8 + 2 * (lane & 3);
                float v0 = (c[mt][idx][2 * e]     - m) * q * Gs[col]     + BEs[col];
                float v1 = (c[mt][idx][2 * e + 1] - m) * q * Gs[col + 1] + BEs[col + 1];
                uint32_t hi, lo;
                split_pair(v0, v1, hi, lo);
                *(uint32_t*)&outHi[(size_t)gr * LAT + col] = hi;
                *(uint32_t*)&outLo[(size_t)gr * LAT + col] = lo;
                if (doYe) {
                    uint32_t off = (uint32_t)((col >> 6) * 16384) +
                                   swz((uint32_t)(row * 128 + (col & 63) * 2));
                    *(uint32_t*)(smp + N_H_HI + off) = hi;
                    *(uint32_t*)(smp + N_H_LO + off) = lo;
                }
            }
        }
    __syncthreads();

    if (doYe) {
#pragma unroll
        for (int mt = 0; mt < 2; mt++)
#pragma unroll
            for (int i = 0; i < 8; i++)
#pragma unroll
                for (int j = 0; j < 4; j++) c[mt][i][j] = 0.f;
        for (int k2 = 0; k2 < 2; k2++) {
            CPA_WAIT(0);
            __syncthreads();
            const uint32_t abH = sb + N_H_HI + k2 * 16384;
            const uint32_t abL = sb + N_H_LO + k2 * 16384;
#pragma unroll
            for (int ks = 0; ks < 4; ks++) {
                const uint32_t kcA = (uint32_t)((ks * 2 + a_kx) * 16) ^ xm;
                const uint32_t kcB = (uint32_t)((ks * 2 + b_kx) * 16) ^ xm;
                uint32_t ah[2][4], al[2][4];
#pragma unroll
                for (int mt = 0; mt < 2; mt++) {
                    uint32_t ro = (uint32_t)((a_row0 + mt * 16) * 128);
                    ldsm4(abH + ro + kcA, ah[mt]);
                    ldsm4(abL + ro + kcA, al[mt]);
                }
#pragma unroll
                for (int g = 0; g < 4; g++) {
                    uint32_t bh[4], bl[4];
                    uint32_t ro = (uint32_t)((b_row0 + g * 16) * 128);
                    ldsm4(sb + N_W2 + ro + kcB, bh);
                    ldsm4(sb + N_W2 + 16384 + ro + kcB, bl);
#pragma unroll
                    for (int mt = 0; mt < 2; mt++)
#pragma unroll
                        for (int hf = 0; hf < 2; hf++) {
                            float* cc = c[mt][g * 2 + hf];
                            mma_bf16(cc, ah[mt], &bh[hf * 2]);
                            mma_bf16(cc, ah[mt], &bl[hf * 2]);
                            mma_bf16(cc, al[mt], &bh[hf * 2]);
                        }
                }
            }
            __syncthreads();
            if (k2 == 0) { fillW1c(1); CPA_COMMIT(); }
        }
#pragma unroll
        for (int mt = 0; mt < 2; mt++)
#pragma unroll
            for (int e = 0; e < 2; e++) {
                int row = mwarp * 32 + mt * 16 + (lane >> 2) + 8 * e;
                int gr = blockRow + row;
                if (gr >= nRows) continue;
#pragma unroll
                for (int idx = 0; idx < 8; idx++) {
                    int col = nwarp * 64 + (idx >> 1) * 16 + (idx & 1) * 8 + 2 * (lane & 3);
                    float2 o;
                    o.x = c[mt][idx][2 * e] + eb1[col];
                    o.y = c[mt][idx][2 * e + 1] + eb1[col + 1];
                    *(float2*)&Ye[(size_t)gr * 128 + col] = o;
                }
            }
    }
}

// ============================================================================
// node_update v3: 2 CTAs/SM + Y12 tail (Y12_next = h_new @ [emW1a|emW1b]).
// ============================================================================
#define U_BUF(b)  ((b) * 32768)
#define U_H_HI    0
#define U_H_LO    32768
#define U_W       65536
#define U_B1      98304
#define U_B2      98816
#define U_G       99328
#define U_BE      99840
#define U_LN      100352
#define SMEM_U    102400

__global__ __launch_bounds__(256, 2) void node_update(
    float* __restrict__ aggF,
    const __nv_bfloat16* __restrict__ hHi, const __nv_bfloat16* __restrict__ hLo,
    const __nv_bfloat16* __restrict__ W1hi, const __nv_bfloat16* __restrict__ W1lo,
    const float* __restrict__ B1,
    const __nv_bfloat16* __restrict__ W2hi, const __nv_bfloat16* __restrict__ W2lo,
    const float* __restrict__ B2,
    const float* __restrict__ G, const float* __restrict__ BE,
    const __nv_bfloat16* __restrict__ resHi, const __nv_bfloat16* __restrict__ resLo,
    __nv_bfloat16* __restrict__ outHi, __nv_bfloat16* __restrict__ outLo,
    const __nv_bfloat16* __restrict__ eW1hi, const __nv_bfloat16* __restrict__ eW1lo,
    float* __restrict__ Y12, int doNext, int nRows)
{
    extern __shared__ char smp[];
    const uint32_t sb = smem_u32(smp);
    const int tid = threadIdx.x;
    const int wid = tid >> 5, lane = tid & 31;
    const int mwarp = wid & 3, nwarp = wid >> 2;
    const int blockRow = blockIdx.x * 128;

    float* b1s = (float*)(smp + U_B1);
    float* b2s = (float*)(smp + U_B2);
    float* Gs  = (float*)(smp + U_G);
    float* BEs = (float*)(smp + U_BE);
    float* lnb = (float*)(smp + U_LN);

    if (tid < 128) {
        b1s[tid] = B1[tid]; b2s[tid] = B2[tid];
        Gs[tid] = G[tid];   BEs[tid] = BE[tid];
    }
    __syncthreads();

    auto fillW1 = [&](int ch) {
#pragma unroll
        for (int p = 0; p < 4; p++) {
            int idx = tid + 256 * p;
            int row = idx >> 3, qq = idx & 7;
            size_t go = (size_t)row * 256 + ch * 64 + qq * 8;
            uint32_t sw = swz((uint32_t)(row * 128 + qq * 16));
            cpa16(sb + U_W + sw, W1hi + go);
            cpa16(sb + U_W + 16384 + sw, W1lo + go);
        }
    };
    auto fillW2c = [&](int ch) {
#pragma unroll
        for (int p = 0; p < 4; p++) {
            int idx = tid + 256 * p;
            int row = idx >> 3, qq = idx & 7;
            size_t go = (size_t)row * 128 + ch * 64 + qq * 8;
            uint32_t sw = swz((uint32_t)(row * 128 + qq * 16));
            cpa16(sb + U_W + sw, W2hi + go);
            cpa16(sb + U_W + 16384 + sw, W2lo + go);
        }
    };
    auto fillTW = [&](int m) {       // emW1 [row][384], cols 0..255 = W1a|W1b
#pragma unroll
        for (int p = 0; p < 4; p++) {
            int idx = tid + 256 * p;
            int row = idx >> 3, qq = idx & 7;
            size_t go = (size_t)row * 384 + m * 64 + qq * 8;
            uint32_t sw = swz((uint32_t)(row * 128 + qq * 16));
            cpa16(sb + U_W + sw, eW1hi + go);
            cpa16(sb + U_W + 16384 + sw, eW1lo + go);
        }
    };
    auto fillA = [&](int ch) {
        const uint32_t bbase = sb + U_BUF(ch & 1);
        char* bptr = smp + U_BUF(ch & 1);
        if (ch < 2) {
            const int koff = ch * 64;
#pragma unroll
            for (int p = 0; p < 8; p++) {
                int idx = tid + 256 * p;
                int row = idx >> 4, f4 = idx & 15;
                int ri = min(blockRow + row, nRows - 1);
                float4 v = *(const float4*)&aggF[(size_t)ri * LAT + koff + f4 * 4];
                uint32_t h0, h1, l0, l1;
                split_pair(v.x, v.y, h0, l0);
                split_pair(v.z, v.w, h1, l1);
                uint32_t sw = swz((uint32_t)(row * 128 + f4 * 8));
                *(uint2*)(bptr + sw) = make_uint2(h0, h1);
                *(uint2*)(bptr + 16384 + sw) = make_uint2(l0, l1);
            }
        } else {
            const int koff = (ch - 2) * 64;
#pragma unroll
            for (int p = 0; p < 4; p++) {
                int idx = tid + 256 * p;
                int row = idx >> 3, q = idx & 7;
                int ri = min(blockRow + row, nRows - 1);
                size_t go = (size_t)ri * LAT + koff + q * 8;
                uint32_t sw = swz((uint32_t)(row * 128 + q * 16));
                cpa16(bbase + sw, hHi + go);
                cpa16(bbase + 16384 + sw, hLo + go);
            }
        }
    };

    const int lrow = lane & 7, lg = lane >> 3;
    const uint32_t xm = (uint32_t)lrow << 4;
    const int a_row0 = mwarp * 32 + lrow + 8 * (lg & 1);
    const int a_kx = lg >> 1;
    const int b_row0 = nwarp * 64 + lrow + 8 * (lg >> 1);
    const int b_kx = lg & 1;

    float c[2][8][4];
#pragma unroll
    for (int mt = 0; mt < 2; mt++)
#pragma unroll
        for (int i = 0; i < 8; i++)
#pragma unroll
            for (int j = 0; j < 4; j++) c[mt][i][j] = 0.f;

    fillW1(0); CPA_COMMIT();

    // ---- layer 1: K=256 in 4 chunks ----
    for (int ch = 0; ch < 4; ch++) {
        fillA(ch);
        if (ch >= 2) CPA_COMMIT();
        CPA_WAIT(0);
        __syncthreads();
        if (ch == 1 && doNext) {   // agg consumed; zero for next step
#pragma unroll
            for (int p = 0; p < 16; p++) {
                int idx = tid + 256 * p;
                int row = idx >> 5, f4 = idx & 31;
                int gr = blockRow + row;
                if (gr < nRows)
                    *(float4*)&aggF[(size_t)gr * LAT + f4 * 4] =
                        make_float4(0.f, 0.f, 0.f, 0.f);
            }
        }
        const uint32_t ab = sb + U_BUF(ch & 1);
#pragma unroll
        for (int ks = 0; ks < 4; ks++) {
            const uint32_t kcA = (uint32_t)((ks * 2 + a_kx) * 16) ^ xm;
            const uint32_t kcB = (uint32_t)((ks * 2 + b_kx) * 16) ^ xm;
            uint32_t ah[2][4], al[2][4];
#pragma unroll
            for (int mt = 0; mt < 2; mt++) {
                uint32_t ro = (uint32_t)((a_row0 + mt * 16) * 128);
                ldsm4(ab + ro + kcA, ah[mt]);
                ldsm4(ab + 16384 + ro + kcA, al[mt]);
            }
#pragma unroll
            for (int g = 0; g < 4; g++) {
                uint32_t bh[4], bl[4];
                uint32_t ro = (uint32_t)((b_row0 + g * 16) * 128);
                ldsm4(sb + U_W + ro + kcB, bh);
                ldsm4(sb + U_W + 16384 + ro + kcB, bl);
#pragma unroll
                for (int mt = 0; mt < 2; mt++)
#pragma unroll
                    for (int hf = 0; hf < 2; hf++) {
                        float* cc = c[mt][g * 2 + hf];
                        mma_bf16(cc, ah[mt], &bh[hf * 2]);
                        mma_bf16(cc, ah[mt], &bl[hf * 2]);
                        mma_bf16(cc, al[mt], &bh[hf * 2]);
                    }
            }
        }
        __syncthreads();
        if (ch < 3) { fillW1(ch + 1); CPA_COMMIT(); }
        else        { fillW2c(0);     CPA_COMMIT(); }
    }

    // hidden -> H planes
#pragma unroll
    for (int mt = 0; mt < 2; mt++)
#pragma unroll
        for (int idx = 0; idx < 8; idx++)
#pragma unroll
            for (int e = 0; e < 2; e++) {
                int row = mwarp * 32 + mt * 16 + (lane >> 2) + 8 * e;
                int col = nwarp * 64 + (idx >> 1) * 16 + (idx & 1) * 8 + 2 * (lane & 3);
                float v0 = fmaxf(c[mt][idx][2 * e] + b1s[col], 0.f);
                float v1 = fmaxf(c[mt][idx][2 * e + 1] + b1s[col + 1], 0.f);
                uint32_t hi, lo;
                split_pair(v0, v1, hi, lo);
                uint32_t off = (uint32_t)(nwarp * 16384 + row * 128 +
                                          (((col & 63) * 2) ^ ((row & 7) << 4)));
                *(uint32_t*)(smp + U_H_HI + off) = hi;
                *(uint32_t*)(smp + U_H_LO + off) = lo;
            }
#pragma unroll
    for (int mt = 0; mt < 2; mt++)
#pragma unroll
        for (int i = 0; i < 8; i++)
#pragma unroll
            for (int j = 0; j < 4; j++) c[mt][i][j] = 0.f;

    // ---- layer 2: K=128 in 2 chunks ----
    for (int c2 = 0; c2 < 2; c2++) {
        CPA_WAIT(0);
        __syncthreads();
        const uint32_t abH = sb + U_H_HI + c2 * 16384;
        const uint32_t abL = sb + U_H_LO + c2 * 16384;
#pragma unroll
        for (int ks = 0; ks < 4; ks++) {
            const uint32_t kcA = (uint32_t)((ks * 2 + a_kx) * 16) ^ xm;
            const uint32_t kcB = (uint32_t)((ks * 2 + b_kx) * 16) ^ xm;
            uint32_t ah[2][4], al[2][4];
#pragma unroll
            for (int mt = 0; mt < 2; mt++) {
                uint32_t ro = (uint32_t)((a_row0 + mt * 16) * 128);
                ldsm4(abH + ro + kcA, ah[mt]);
                ldsm4(abL + ro + kcA, al[mt]);
            }
#pragma unroll
            for (int g = 0; g < 4; g++) {
                uint32_t bh[4], bl[4];
                uint32_t ro = (uint32_t)((b_row0 + g * 16) * 128);
                ldsm4(sb + U_W + ro + kcB, bh);
                ldsm4(sb + U_W + 16384 + ro + kcB, bl);
#pragma unroll
                for (int mt = 0; mt < 2; mt++)
#pragma unroll
                    for (int hf = 0; hf < 2; hf++) {
                        float* cc = c[mt][g * 2 + hf];
                        mma_bf16(cc, ah[mt], &bh[hf * 2]);
                        mma_bf16(cc, ah[mt], &bl[hf * 2]);
                        mma_bf16(cc, al[mt], &bh[hf * 2]);
                    }
            }
        }
        __syncthreads();
        if (c2 == 0) { fillW2c(1); CPA_COMMIT(); }
    }

    // bias2 + ReLU + LN
#pragma unroll
    for (int mt = 0; mt < 2; mt++)
#pragma unroll
        for (int idx = 0; idx < 8; idx++) {
            int col = nwarp * 64 + (idx >> 1) * 16 + (idx & 1) * 8 + 2 * (lane & 3);
#pragma unroll
            for (int j = 0; j < 4; j++)
                c[mt][idx][j] = fmaxf(c[mt][idx][j] + b2s[col + (j & 1)], 0.f);
        }

#pragma unroll
    for (int mt = 0; mt < 2; mt++)
#pragma unroll
        for (int e = 0; e < 2; e++) {
            float s = 0.f;
#pragma unroll
            for (int idx = 0; idx < 8; idx++)
                s += c[mt][idx][2 * e] + c[mt][idx][2 * e + 1];
            s += __shfl_xor_sync(0xffffffffu, s, 1);
            s += __shfl_xor_sync(0xffffffffu, s, 2);
            if ((lane & 3) == 0) {
                int row = mwarp * 32 + mt * 16 + (lane >> 2) + 8 * e;
                lnb[row * 2 + nwarp] = s;
            }
        }
    __syncthreads();
    float mu[2][2], rs[2][2];
#pragma unroll
    for (int mt = 0; mt < 2; mt++)
#pragma unroll
        for (int e = 0; e < 2; e++) {
            int row = mwarp * 32 + mt * 16 + (lane >> 2) + 8 * e;
            mu[mt][e] = (lnb[row * 2] + lnb[row * 2 + 1]) * (1.0f / 128.0f);
            float sq = 0.f;
#pragma unroll
            for (int idx = 0; idx < 8; idx++) {
                float d0 = c[mt][idx][2 * e] - mu[mt][e];
                float d1 = c[mt][idx][2 * e + 1] - mu[mt][e];
                sq = fmaf(d0, d0, sq);
                sq = fmaf(d1, d1, sq);
            }
            sq += __shfl_xor_sync(0xffffffffu, sq, 1);
            sq += __shfl_xor_sync(0xffffffffu, sq, 2);
            if ((lane & 3) == 0) lnb[256 + row * 2 + nwarp] = sq;
        }
    __syncthreads();
#pragma unroll
    for (int mt = 0; mt < 2; mt++)
#pragma unroll
        for (int e = 0; e < 2; e++) {
            int row = mwarp * 32 + mt * 16 + (lane >> 2) + 8 * e;
            rs[mt][e] = rsqrtf((lnb[256 + row * 2] + lnb[256 + row * 2 + 1]) *
                                   (1.0f / 128.0f) + EPSV);
        }

    // output (+ stash h_new splits for Y12 tail)
#pragma unroll
    for (int mt = 0; mt < 2; mt++)
#pragma unroll
        for (int e = 0; e < 2; e++) {
            int row = mwarp * 32 + mt * 16 + (lane >> 2) + 8 * e;
            int gr = blockRow + row;
            if (gr >= nRows) continue;
            float m = mu[mt][e], q = rs[mt][e];
#pragma unroll
            for (int idx = 0; idx < 8; idx++) {
                int col = nwarp * 64 + (idx >> 1) * 16 + (idx & 1) * 8 + 2 * (lane & 3);
                float v0 = (c[mt][idx][2 * e]     - m) * q * Gs[col]     + BEs[col];
                float v1 = (c[mt][idx][2 * e + 1] - m) * q * Gs[col + 1] + BEs[col + 1];
                uint32_t rh = *(const uint32_t*)&resHi[(size_t)gr * LAT + col];
                uint32_t rl = *(const uint32_t*)&resLo[(size_t)gr * LAT + col];
                v0 += recon(rh, 0) + recon(rl, 0);
                v1 += recon(rh, 1) + recon(rl, 1);
                uint32_t hi, lo;
                split_pair(v0, v1, hi, lo);
                *(uint32_t*)&outHi[(size_t)gr * LAT + col] = hi;
                *(uint32_t*)&outLo[(size_t)gr * LAT + col] = lo;
                if (doNext) {
                    uint32_t off = (uint32_t)(nwarp * 16384 + row * 128 +
                                              (((col & 63) * 2) ^ ((row & 7) << 4)));
                    *(uint32_t*)(smp + U_H_HI + off) = hi;
                    *(uint32_t*)(smp + U_H_LO + off) = lo;
                }
            }
        }

    // ---- Y12 tail: Y12_next = h_new @ [emW1a | emW1b] ----
    if (doNext) {
        __syncthreads();           // stashes visible; U_W chunk-1 reads drained
        fillTW(0); CPA_COMMIT();
        for (int blk = 0; blk < 2; blk++) {
#pragma unroll
            for (int mt = 0; mt < 2; mt++)
#pragma unroll
                for (int i = 0; i < 8; i++)
#pragma unroll
                    for (int j = 0; j < 4; j++) c[mt][i][j] = 0.f;
            for (int k2 = 0; k2 < 2; k2++) {
                CPA_WAIT(0);
                __syncthreads();
                const uint32_t abH = sb + U_H_HI + k2 * 16384;
                const uint32_t abL = sb + U_H_LO + k2 * 16384;
#pragma unroll
                for (int ks = 0; ks < 4; ks++) {
                    const uint32_t kcA = (uint32_t)((ks * 2 + a_kx) * 16) ^ xm;
                    const uint32_t kcB = (uint32_t)((ks * 2 + b_kx) * 16) ^ xm;
                    uint32_t ah[2][4], al[2][4];
#pragma unroll
                    for (int mt = 0; mt < 2; mt++) {
                        uint32_t ro = (uint32_t)((a_row0 + mt * 16) * 128);
                        ldsm4(abH + ro + kcA, ah[mt]);
                        ldsm4(abL + ro + kcA, al[mt]);
                    }
#pragma unroll
                    for (int g = 0; g < 4; g++) {
                        uint32_t bh[4], bl[4];
                        uint32_t ro = (uint32_t)((b_row0 + g * 16) * 128);
                        ldsm4(sb + U_W + ro + kcB, bh);
                        ldsm4(sb + U_W + 16384 + ro + kcB, bl);
#pragma unroll
                        for (int mt = 0; mt < 2; mt++)
#pragma unroll
                            for (int hf = 0; hf < 2; hf++) {
                                float* cc = c[mt][g * 2 + hf];
                                mma_bf16(cc, ah[mt], &bh[hf * 2]);
                                mma_bf16(cc, ah[mt], &bl[hf * 2]);
                                mma_bf16(cc, al[mt], &bh[hf * 2]);
                            }
                    }
                }
                __syncthreads();
                int m = blk * 2 + k2;
                if (m < 3) { fillTW(m + 1); CPA_COMMIT(); }
            }
#pragma unroll
            for (int mt = 0; mt < 2; mt++)
#pragma unroll
                for (int e = 0; e < 2; e++) {
                    int row = mwarp * 32 + mt * 16 + (lane >> 2) + 8 * e;
                    int gr = blockRow + row;
                    if (gr >= nRows) continue;
#pragma unroll
                    for (int idx = 0; idx < 8; idx++) {
                        int col = nwarp * 64 + (idx >> 1) * 16 + (idx & 1) * 8 + 2 * (lane & 3);
                        float2 o;
                        o.x = c[mt][idx][2 * e];
                        o.y = c[mt][idx][2 * e + 1];
                        *(float2*)&Y12[(size_t)gr * 256 + blk * 128 + col] = o;
                    }
                }
        }
    }
}

__global__ void prep_all(
    const float* __restrict__ s0, __nv_bfloat16* __restrict__ h0b, __nv_bfloat16* __restrict__ l0b,
    const float* __restrict__ s1, __nv_bfloat16* __restrict__ h1b, __nv_bfloat16* __restrict__ l1b,
    const float* __restrict__ s2, __nv_bfloat16* __restrict__ h2b, __nv_bfloat16* __restrict__ l2b,
    const float* __restrict__ s3, __nv_bfloat16* __restrict__ h3b, __nv_bfloat16* __restrict__ l3b,
    const float* __restrict__ s4, __nv_bfloat16* __restrict__ h4b, __nv_bfloat16* __restrict__ l4b,
    const float* __restrict__ s5, __nv_bfloat16* __restrict__ h5b, __nv_bfloat16* __restrict__ l5b)
{
    int i = blockIdx.x * blockDim.x + threadIdx.x;
    const float* W; __nv_bfloat16 *hi, *lo; int K, j;
    if (i < 49152)       { W = s0; hi = h0b; lo = l0b; K = 384; j = i; }
    else if (i < 65536)  { W = s1; hi = h1b; lo = l1b; K = 128; j = i - 49152; }
    else if (i < 98304)  { W = s2; hi = h2b; lo = l2b; K = 256; j = i - 65536; }
    else if (i < 114688) { W = s3; hi = h3b; lo = l3b; K = 128; j = i - 98304; }
    else if (i < 131072) { W = s4; hi = h4b; lo = l4b; K = 128; j = i - 114688; }
    else if (i < 147456) { W = s5; hi = h5b; lo = l5b; K = 128; j = i - 131072; }
    else return;
    int k = j >> 7, n = j & 127;
    float v = W[j];
    __nv_bfloat16 h = __float2bfloat16(v);
    hi[(size_t)n * K + k] = h;
    lo[(size_t)n * K + k] = __float2bfloat16(v - __bfloat162float(h));
}

__global__ __launch_bounds__(256) void decoder_kernel(
    const __nv_bfloat16* __restrict__ hHi, const __nv_bfloat16* __restrict__ hLo,
    const float* __restrict__ W1, const float* __restrict__ B1,
    const float* __restrict__ W2, const float* __restrict__ B2,
    float* __restrict__ out, int n)
{
    extern __shared__ float s[];
    float* W1s = s;
    float* hs = s + 128 * 128;
    int tid = threadIdx.x;
#pragma unroll
    for (int it = 0; it < 16; it++) {
        int f = tid + 256 * it;
        *(float4*)&W1s[f * 4] = *(const float4*)&W1[f * 4];
    }
    int warp = tid >> 5, lane = tid & 31;
    int row = blockIdx.x * 8 + warp;
    int rc = min(row, n - 1);
#pragma unroll
    for (int q = 0; q < 4; q++) {
        int cc = lane + 32 * q;
        hs[warp * 128 + cc] = __bfloat162float(hHi[(size_t)rc * LAT + cc]) +
                              __bfloat162float(hLo[(size_t)rc * LAT + cc]);
    }
    __syncthreads();

    float acc[4];
#pragma unroll
    for (int q = 0; q < 4; q++) acc[q] = B1[lane + 32 * q];
    for (int k = 0; k < 128; k++) {
        float hv = hs[warp * 128 + k];
#pragma unroll
        for (int q = 0; q < 4; q++)
            acc[q] = fmaf(hv, W1s[k * 128 + lane + 32 * q], acc[q]);
    }
#pragma unroll
    for (int q = 0; q < 4; q++) acc[q] = fmaxf(acc[q], 0.f);

    float o[3];
#pragma unroll
    for (int oo = 0; oo < 3; oo++) {
        float p = 0.f;
#pragma unroll
        for (int q = 0; q < 4; q++)
            p = fmaf(acc[q], W2[(size_t)(lane + 32 * q) * 3 + oo], p);
#pragma unroll
        for (int off = 16; off > 0; off >>= 1)
            p += __shfl_xor_sync(0xffffffffu, p, off);
        o[oo] = p;
    }
    if (lane == 0 && row < n) {
        out[(size_t)row * 3 + 0] = o[0] + B2[0];
        out[(size_t)row * 3 + 1] = o[1] + B2[1];
        out[(size_t)row * 3 + 2] = o[2] + B2[2];
    }
}

__global__ void zero_kernel(float4* __restrict__ p, int n4)
{
    int i = blockIdx.x * blockDim.x + threadIdx.x;
    if (i < n4) p[i] = make_float4(0.f, 0.f, 0.f, 0.f);
}

extern "C" void kernel_launch(void* const* d_in, const int* in_sizes, int n_in,
                              void* d_out, int out_size)
{
    (void)in_sizes; (void)n_in; (void)out_size;
    const float* x  = (const float*)d_in[0];
    const float* ea = (const float*)d_in[1];
    const int*   ei = (const int*)d_in[2];
    const int* src = ei;
    const int* dst = ei + NEDGES;

    const float* ne_w1 = (const float*)d_in[3];
    const float* ne_b1 = (const float*)d_in[4];
    const float* ne_w2 = (const float*)d_in[5];
    const float* ne_b2 = (const float*)d_in[6];
    const float* ne_g  = (const float*)d_in[7];
    const float* ne_be = (const float*)d_in[8];
    const float* ee_w1 = (const float*)d_in[9];
    const float* ee_b1 = (const float*)d_in[10];
    const float* ee_w2 = (const float*)d_in[11];
    const float* ee_b2 = (const float*)d_in[12];
    const float* ee_g  = (const float*)d_in[13];
    const float* ee_be = (const float*)d_in[14];
    const float* em_w1 = (const float*)d_in[15];
    const float* em_b1 = (const float*)d_in[16];
    const float* em_w2 = (const float*)d_in[17];
    const float* em_b2 = (const float*)d_in[18];
    const float* em_g  = (const float*)d_in[19];
    const float* em_be = (const float*)d_in[20];
    const float* nm_w1 = (const float*)d_in[21];
    const float* nm_b1 = (const float*)d_in[22];
    const float* nm_w2 = (const float*)d_in[23];
    const float* nm_b2 = (const float*)d_in[24];
    const float* nm_g  = (const float*)d_in[25];
    const float* nm_be = (const float*)d_in[26];
    const float* dw1   = (const float*)d_in[27];
    const float* db1   = (const float*)d_in[28];
    const float* dw2   = (const float*)d_in[29];
    const float* db2   = (const float*)d_in[30];

    float* fb = nullptr;
    cudaGetSymbolAddress((void**)&fb, g_fbuf);
    float* agg = fb;
    float* Y12 = fb + (size_t)NNODES * LAT;
    float* Ye  = fb + (size_t)3 * NNODES * LAT;

    __nv_bfloat16* hp = nullptr;
    cudaGetSymbolAddress((void**)&hp, g_hpl);
    __nv_bfloat16* ep = nullptr;
    cudaGetSymbolAddress((void**)&ep, g_epl);
    const size_t HS = (size_t)NNODES * LAT, ES = (size_t)NEDGES * LAT;
    __nv_bfloat16 *hH0 = hp, *hL0 = hp + HS, *hH1 = hp + 2 * HS, *hL1 = hp + 3 * HS;
    __nv_bfloat16 *eH0 = ep, *eL0 = ep + ES, *eH1 = ep + 2 * ES, *eL1 = ep + 3 * ES;

    __nv_bfloat16* pl = nullptr;
    cudaGetSymbolAddress((void**)&pl, g_planes);
    __nv_bfloat16* emW1h = pl;
    __nv_bfloat16* emW1l = pl + 49152;
    __nv_bfloat16* emW2h = pl + 98304;
    __nv_bfloat16* emW2l = pl + 114688;
    __nv_bfloat16* nmW1h = pl + 131072;
    __nv_bfloat16* nmW1l = pl + 163840;
    __nv_bfloat16* nmW2h = pl + 196608;
    __nv_bfloat16* nmW2l = pl + 212992;
    __nv_bfloat16* neW2h = pl + 229376;
    __nv_bfloat16* neW2l = pl + 245760;
    __nv_bfloat16* eeW2h = pl + 262144;
    __nv_bfloat16* eeW2l = pl + 278528;

    cudaFuncSetAttribute(node_update,
                         cudaFuncAttributeMaxDynamicSharedMemorySize, SMEM_U);
    cudaFuncSetAttribute(edge_fused,
                         cudaFuncAttributeMaxDynamicSharedMemorySize, SMEM_E);
    cudaFuncSetAttribute(gemm_y12,
                         cudaFuncAttributeMaxDynamicSharedMemorySize, SMEM_Y);
    cudaFuncSetAttribute(encode_mlp,
                         cudaFuncAttributeMaxDynamicSharedMemorySize, SMEM_N);
    const int DSM = (128 * 128 + 8 * 128) * (int)sizeof(float);
    cudaFuncSetAttribute(decoder_kernel,
                         cudaFuncAttributeMaxDynamicSharedMemorySize, DSM);

    prep_all<<<(147456 + 255) / 256, 256>>>(
        em_w1, emW1h, emW1l, em_w2, emW2h, emW2l,
        nm_w1, nmW1h, nmW1l, nm_w2, nmW2h, nmW2l,
        ne_w2, neW2h, neW2l, ee_w2, eeW2h, eeW2l);

    dim3 blk(256);
    const int ntiles = (NNODES + 127) / 128;  // 391
    const int etiles = NEDGES / 128;          // 3125

    encode_mlp<<<ntiles, blk, SMEM_N>>>(
        x, ne_w1, 3, ne_b1, neW2h, neW2l, ne_b2, ne_g, ne_be,
        nullptr, nullptr, nullptr, nullptr, 0, hH0, hL0, NNODES);
    encode_mlp<<<etiles, blk, SMEM_N>>>(
        ea, ee_w1, 4, ee_b1, eeW2h, eeW2l, ee_b2, ee_g, ee_be,
        emW1h, emW1l, em_b1, Ye, 1, eH0, eL0, NEDGES);
    zero_kernel<<<(NNODES * LAT / 4 + 255) / 256, 256>>>((float4*)agg,
                                                         NNODES * LAT / 4);
    gemm_y12<<<ntiles, blk, SMEM_Y>>>(hH0, hL0, emW1h, emW1l, Y12, NNODES);

    __nv_bfloat16 *hcH = hH0, *hcL = hL0, *hnH = hH1, *hnL = hL1;
    __nv_bfloat16 *ecH = eH0, *ecL = eL0, *enH = eH1, *enL = eL1;
    for (int s = 0; s < 5; s++) {
        edge_fused<<<etiles, blk, SMEM_E>>>(
            Y12, Ye, dst, src, emW2h, emW2l, em_b2, em_g, em_be,
            emW1h, emW1l, em_b1,
            ecH, ecL, enH, enL, agg, (s < 4) ? 1 : 0, NEDGES);
        node_update<<<ntiles, blk, SMEM_U>>>(
            agg, hcH, hcL, nmW1h, nmW1l, nm_b1, nmW2h, nmW2l, nm_b2, nm_g, nm_be,
            hcH, hcL, hnH, hnL,
            emW1h, emW1l, Y12, (s < 4) ? 1 : 0, NNODES);
        __nv_bfloat16* t;
        t = hcH; hcH = hnH; hnH = t;
        t = hcL; hcL = hnL; hnL = t;
        t = ecH; ecH = enH; enH = t;
        t = ecL; ecL = enL; enL = t;
    }

    decoder_kernel<<<(NNODES + 7) / 8, blk, DSM>>>(
        hcH, hcL, dw1, db1, dw2, db2, (float*)d_out, NNODES);
}

// round 17
// speedup vs baseline: 1.0101x; 1.0101x over previous
#include <cuda_runtime.h>
#include <cuda_bf16.h>
#include <cstdint>
#include <cstddef>

#define LAT 128
#define NNODES 50000
#define NEDGES 400000
#define EPSV 1e-5f

// fp32: agg | Y12 [N,256] | Ye [E,128]
__device__ float g_fbuf[(size_t)(3 * NNODES + NEDGES) * LAT];
__device__ __align__(16) __nv_bfloat16 g_hpl[(size_t)4 * NNODES * LAT];
__device__ __align__(16) __nv_bfloat16 g_epl[(size_t)4 * NEDGES * LAT];
__device__ __align__(16) __nv_bfloat16 g_planes[294912];

__device__ __forceinline__ uint32_t smem_u32(const void* p) {
    uint32_t a;
    asm("{ .reg .u64 t; cvta.to.shared.u64 t, %1; cvt.u32.u64 %0, t; }" : "=r"(a) : "l"(p));
    return a;
}
__device__ __forceinline__ void ldsm4(uint32_t addr, uint32_t* r) {
    asm volatile("ldmatrix.sync.aligned.m8n8.x4.shared.b16 {%0,%1,%2,%3}, [%4];"
                 : "=r"(r[0]), "=r"(r[1]), "=r"(r[2]), "=r"(r[3]) : "r"(addr));
}
__device__ __forceinline__ void mma_bf16(float* d, const uint32_t* a, const uint32_t* b) {
    asm volatile("mma.sync.aligned.m16n8k16.row.col.f32.bf16.bf16.f32 "
                 "{%0,%1,%2,%3}, {%4,%5,%6,%7}, {%8,%9}, {%0,%1,%2,%3};"
                 : "+f"(d[0]), "+f"(d[1]), "+f"(d[2]), "+f"(d[3])
                 : "r"(a[0]), "r"(a[1]), "r"(a[2]), "r"(a[3]), "r"(b[0]), "r"(b[1]));
}
__device__ __forceinline__ void cpa16(uint32_t saddr, const void* g) {
    asm volatile("cp.async.cg.shared.global [%0], [%1], 16;"
                 :: "r"(saddr), "l"(g) : "memory");
}
#define CPA_COMMIT() asm volatile("cp.async.commit_group;" ::: "memory")
#define CPA_WAIT(N)  asm volatile("cp.async.wait_group %0;" :: "n"(N) : "memory")
__device__ __forceinline__ void red2(float* addr, float v0, float v1) {
    asm volatile("red.global.add.v2.f32 [%0], {%1, %2};"
                 :: "l"(addr), "f"(v0), "f"(v1) : "memory");
}
__device__ __forceinline__ uint32_t swz(uint32_t bo) { return bo ^ ((bo >> 3) & 0x70); }
__device__ __forceinline__ void split_pair(float a, float b, uint32_t& hi, uint32_t& lo) {
    __nv_bfloat16 ah = __float2bfloat16(a), bh = __float2bfloat16(b);
    __nv_bfloat162 hp; hp.x = ah; hp.y = bh;
    __nv_bfloat162 lp;
    lp.x = __float2bfloat16(a - __bfloat162float(ah));
    lp.y = __float2bfloat16(b - __bfloat162float(bh));
    hi = *reinterpret_cast<uint32_t*>(&hp);
    lo = *reinterpret_cast<uint32_t*>(&lp);
}
__device__ __forceinline__ float recon(uint32_t packed, int half) {
    __nv_bfloat162 v = *reinterpret_cast<__nv_bfloat162*>(&packed);
    return half ? __bfloat162float(v.y) : __bfloat162float(v.x);
}

// ============================================================================
// gemm_y12 (per step): Y12[r,0:128]=h@W1a ; Y12[r,128:256]=h@W1b
// ============================================================================
#define Y_A_HI 0
#define Y_A_LO 32768
#define Y_B_HI 65536
#define Y_B_LO 81920
#define SMEM_Y 98304

__global__ __launch_bounds__(256, 2) void gemm_y12(
    const __nv_bfloat16* __restrict__ aHi, const __nv_bfloat16* __restrict__ aLo,
    const __nv_bfloat16* __restrict__ bHi, const __nv_bfloat16* __restrict__ bLo,
    float* __restrict__ out, int nRows)
{
    extern __shared__ char smp[];
    const uint32_t sb = smem_u32(smp);
    const int tid = threadIdx.x;
    const int wid = tid >> 5, lane = tid & 31;
    const int mwarp = wid & 3, nwarp = wid >> 2;
    const int blockRow = blockIdx.x * 128;

#pragma unroll
    for (int p = 0; p < 8; p++) {
        int idx = tid + 256 * p;
        int row = idx >> 4, q = idx & 15;
        int c2 = q >> 3, qq = q & 7;
        int rc = min(blockRow + row, nRows - 1);
        size_t ga = (size_t)rc * 128 + q * 8;
        uint32_t sw = (uint32_t)(c2 * 16384) + swz((uint32_t)(row * 128 + qq * 16));
        cpa16(sb + Y_A_HI + sw, aHi + ga);
        cpa16(sb + Y_A_LO + sw, aLo + ga);
    }
    auto fillB = [&](int m) {
#pragma unroll
        for (int p = 0; p < 4; p++) {
            int idx = tid + 256 * p;
            int row = idx >> 3, qq = idx & 7;
            size_t gb = (size_t)row * 384 + m * 64 + qq * 8;
            uint32_t sw = swz((uint32_t)(row * 128 + qq * 16));
            cpa16(sb + Y_B_HI + sw, bHi + gb);
            cpa16(sb + Y_B_LO + sw, bLo + gb);
        }
    };
    fillB(0);
    CPA_COMMIT();

    const int lrow = lane & 7, lg = lane >> 3;
    const uint32_t xm = (uint32_t)lrow << 4;
    const int a_row0 = mwarp * 32 + lrow + 8 * (lg & 1);
    const int a_kx = lg >> 1;
    const int b_row0 = nwarp * 64 + lrow + 8 * (lg >> 1);
    const int b_kx = lg & 1;

    for (int blk = 0; blk < 2; blk++) {
        float c[2][8][4];
#pragma unroll
        for (int mt = 0; mt < 2; mt++)
#pragma unroll
            for (int i = 0; i < 8; i++)
#pragma unroll
                for (int j = 0; j < 4; j++) c[mt][i][j] = 0.f;

        for (int c2 = 0; c2 < 2; c2++) {
            CPA_WAIT(0);
            __syncthreads();
            const uint32_t abH = sb + Y_A_HI + c2 * 16384;
            const uint32_t abL = sb + Y_A_LO + c2 * 16384;
#pragma unroll
            for (int ks = 0; ks < 4; ks++) {
                const uint32_t kcA = (uint32_t)((ks * 2 + a_kx) * 16) ^ xm;
                const uint32_t kcB = (uint32_t)((ks * 2 + b_kx) * 16) ^ xm;
                uint32_t ah[2][4], al[2][4];
#pragma unroll
                for (int mt = 0; mt < 2; mt++) {
                    uint32_t ro = (uint32_t)((a_row0 + mt * 16) * 128);
                    ldsm4(abH + ro + kcA, ah[mt]);
                    ldsm4(abL + ro + kcA, al[mt]);
                }
#pragma unroll
                for (int g = 0; g < 4; g++) {
                    uint32_t bh[4], bl[4];
                    uint32_t ro = (uint32_t)((b_row0 + g * 16) * 128);
                    ldsm4(sb + Y_B_HI + ro + kcB, bh);
                    ldsm4(sb + Y_B_LO + ro + kcB, bl);
#pragma unroll
                    for (int mt = 0; mt < 2; mt++)
#pragma unroll
                        for (int hf = 0; hf < 2; hf++) {
                            float* cc = c[mt][g * 2 + hf];
                            mma_bf16(cc, ah[mt], &bh[hf * 2]);
                            mma_bf16(cc, ah[mt], &bl[hf * 2]);
                            mma_bf16(cc, al[mt], &bh[hf * 2]);
                        }
                }
            }
            __syncthreads();
            int m = blk * 2 + c2;
            if (m < 3) { fillB(m + 1); CPA_COMMIT(); }
        }

#pragma unroll
        for (int mt = 0; mt < 2; mt++)
#pragma unroll
            for (int e = 0; e < 2; e++) {
                int row = mwarp * 32 + mt * 16 + (lane >> 2) + 8 * e;
                int gr = blockRow + row;
                if (gr >= nRows) continue;
#pragma unroll
                for (int idx = 0; idx < 8; idx++) {
                    int col = nwarp * 64 + (idx >> 1) * 16 + (idx & 1) * 8 + 2 * (lane & 3);
                    float2 o;
                    o.x = c[mt][idx][2 * e];
                    o.y = c[mt][idx][2 * e + 1];
                    *(float2*)&out[(size_t)gr * 256 + blk * 128 + col] = o;
                }
            }
    }
}

// ============================================================================
// edge_fused: MSG scatter [+ EDGE update + Ye tail when doTail]
// ============================================================================
#define E_H_HI 0
#define E_H_LO 32768
#define E_W2   65536
#define E_IDX  98304
#define E_B2   99328
#define E_G    99840
#define E_BE   100352
#define E_B1   100864
#define E_LN   101376
#define SMEM_E 103424

__global__ __launch_bounds__(256, 2) void edge_fused(
    const float* __restrict__ Y12, float* __restrict__ Ye,
    const int* __restrict__ dst, const int* __restrict__ src,
    const __nv_bfloat16* __restrict__ W2hi, const __nv_bfloat16* __restrict__ W2lo,
    const float* __restrict__ B2, const float* __restrict__ G,
    const float* __restrict__ BE,
    const __nv_bfloat16* __restrict__ W1hi, const __nv_bfloat16* __restrict__ W1lo,
    const float* __restrict__ B1,
    const __nv_bfloat16* __restrict__ resHi, const __nv_bfloat16* __restrict__ resLo,
    __nv_bfloat16* __restrict__ outHi, __nv_bfloat16* __restrict__ outLo,
    float* __restrict__ aggF, int doTail, int nRows)
{
    extern __shared__ char smp[];
    const uint32_t sb = smem_u32(smp);
    const int tid = threadIdx.x;
    const int wid = tid >> 5, lane = tid & 31;
    const int mwarp = wid & 3, nwarp = wid >> 2;
    const int blockRow = blockIdx.x * 128;

    int* idxs = (int*)(smp + E_IDX);
    float* b2s = (float*)(smp + E_B2);
    float* Gs  = (float*)(smp + E_G);
    float* BEs = (float*)(smp + E_BE);
    float* b1s = (float*)(smp + E_B1);
    float* lnb = (float*)(smp + E_LN);

    if (tid < 128) {
        idxs[tid] = dst[min(blockRow + tid, nRows - 1)];
        b2s[tid] = B2[tid]; Gs[tid] = G[tid]; BEs[tid] = BE[tid];
        b1s[tid] = B1[tid];
    } else {
        idxs[tid] = src[min(blockRow + tid - 128, nRows - 1)];
    }
    __syncthreads();

    auto fillW2 = [&](int chunk) {
#pragma unroll
        for (int p = 0; p < 4; p++) {
            int idx = tid + 256 * p;
            int row = idx >> 3, qq = idx & 7;
            size_t go = (size_t)row * 128 + chunk * 64 + qq * 8;
            uint32_t sw = swz((uint32_t)(row * 128 + qq * 16));
            cpa16(sb + E_W2 + sw, W2hi + go);
            cpa16(sb + E_W2 + 16384 + sw, W2lo + go);
        }
    };
    auto fillW1c = [&](int chunk) {
#pragma unroll
        for (int p = 0; p < 4; p++) {
            int idx = tid + 256 * p;
            int row = idx >> 3, qq = idx & 7;
            size_t go = (size_t)row * 384 + 256 + chunk * 64 + qq * 8;
            uint32_t sw = swz((uint32_t)(row * 128 + qq * 16));
            cpa16(sb + E_W2 + sw, W1hi + go);
            cpa16(sb + E_W2 + 16384 + sw, W1lo + go);
        }
    };
    fillW2(0); CPA_COMMIT();

    const int lrow = lane & 7, lg = lane >> 3;
    const uint32_t xm = (uint32_t)lrow << 4;
    const int a_row0 = mwarp * 32 + lrow + 8 * (lg & 1);
    const int a_kx = lg >> 1;
    const int b_row0 = nwarp * 64 + lrow + 8 * (lg >> 1);
    const int b_kx = lg & 1;

    const int nPh = doTail ? 2 : 1;
    for (int ph = 0; ph < nPh; ph++) {
        const bool MSG = (ph == 0);
#pragma unroll 4
        for (int p = 0; p < 16; p++) {
            int idx = tid + 256 * p;
            int row = idx >> 5, qf = idx & 31;
            int col = qf * 4;
            int gr = min(blockRow + row, nRows - 1);
            int riA = MSG ? idxs[row] : idxs[128 + row];
            int riB = MSG ? idxs[128 + row] : idxs[row];
            float4 a = *(const float4*)&Y12[(size_t)riA * 256 + col];
            float4 b = *(const float4*)&Y12[(size_t)riB * 256 + 128 + col];
            float4 e4 = *(const float4*)&Ye[(size_t)gr * 128 + col];
            float v0 = fmaxf(a.x + b.x + e4.x, 0.f);
            float v1 = fmaxf(a.y + b.y + e4.y, 0.f);
            float v2 = fmaxf(a.z + b.z + e4.z, 0.f);
            float v3 = fmaxf(a.w + b.w + e4.w, 0.f);
            uint32_t h0, h1, l0, l1;
            split_pair(v0, v1, h0, l0);
            split_pair(v2, v3, h1, l1);
            uint32_t off = (uint32_t)((col >> 6) * 16384) +
                           swz((uint32_t)(row * 128 + (col & 63) * 2));
            *(uint2*)(smp + E_H_HI + off) = make_uint2(h0, h1);
            *(uint2*)(smp + E_H_LO + off) = make_uint2(l0, l1);
        }

        float c[2][8][4];
#pragma unroll
        for (int mt = 0; mt < 2; mt++)
#pragma unroll
            for (int i = 0; i < 8; i++)
#pragma unroll
                for (int j = 0; j < 4; j++) c[mt][i][j] = 0.f;

        for (int c2 = 0; c2 < 2; c2++) {
            CPA_WAIT(0);
            __syncthreads();
            const uint32_t abH = sb + E_H_HI + c2 * 16384;
            const uint32_t abL = sb + E_H_LO + c2 * 16384;
#pragma unroll
            for (int ks = 0; ks < 4; ks++) {
                const uint32_t kcA = (uint32_t)((ks * 2 + a_kx) * 16) ^ xm;
                const uint32_t kcB = (uint32_t)((ks * 2 + b_kx) * 16) ^ xm;
                uint32_t ah[2][4], al[2][4];
#pragma unroll
                for (int mt = 0; mt < 2; mt++) {
                    uint32_t ro = (uint32_t)((a_row0 + mt * 16) * 128);
                    ldsm4(abH + ro + kcA, ah[mt]);
                    ldsm4(abL + ro + kcA, al[mt]);
                }
#pragma unroll
                for (int g = 0; g < 4; g++) {
                    uint32_t bh[4], bl[4];
                    uint32_t ro = (uint32_t)((b_row0 + g * 16) * 128);
                    ldsm4(sb + E_W2 + ro + kcB, bh);
                    ldsm4(sb + E_W2 + 16384 + ro + kcB, bl);
#pragma unroll
                    for (int mt = 0; mt < 2; mt++)
#pragma unroll
                        for (int hf = 0; hf < 2; hf++) {
                            float* cc = c[mt][g * 2 + hf];
                            mma_bf16(cc, ah[mt], &bh[hf * 2]);
                            mma_bf16(cc, ah[mt], &bl[hf * 2]);
                            mma_bf16(cc, al[mt], &bh[hf * 2]);
                        }
                }
            }
            __syncthreads();
            if (c2 == 0) { fillW2(1); CPA_COMMIT(); }
            else if (MSG && doTail) { fillW2(0); CPA_COMMIT(); }
            else if (!MSG) { fillW1c(0); CPA_COMMIT(); }
        }

#pragma unroll
        for (int mt = 0; mt < 2; mt++)
#pragma unroll
            for (int idx = 0; idx < 8; idx++) {
                int col = nwarp * 64 + (idx >> 1) * 16 + (idx & 1) * 8 + 2 * (lane & 3);
#pragma unroll
                for (int j = 0; j < 4; j++)
                    c[mt][idx][j] = fmaxf(c[mt][idx][j] + b2s[col + (j & 1)], 0.f);
            }

#pragma unroll
        for (int mt = 0; mt < 2; mt++)
#pragma unroll
            for (int e = 0; e < 2; e++) {
                float s = 0.f;
#pragma unroll
                for (int idx = 0; idx < 8; idx++)
                    s += c[mt][idx][2 * e] + c[mt][idx][2 * e + 1];
                s += __shfl_xor_sync(0xffffffffu, s, 1);
                s += __shfl_xor_sync(0xffffffffu, s, 2);
                if ((lane & 3) == 0) {
                    int row = mwarp * 32 + mt * 16 + (lane >> 2) + 8 * e;
                    lnb[row * 2 + nwarp] = s;
                }
            }
        __syncthreads();
        float mu[2][2], rs[2][2];
#pragma unroll
        for (int mt = 0; mt < 2; mt++)
#pragma unroll
            for (int e = 0; e < 2; e++) {
                int row = mwarp * 32 + mt * 16 + (lane >> 2) + 8 * e;
                mu[mt][e] = (lnb[row * 2] + lnb[row * 2 + 1]) * (1.0f / 128.0f);
                float sq = 0.f;
#pragma unroll
                for (int idx = 0; idx < 8; idx++) {
                    float d0 = c[mt][idx][2 * e] - mu[mt][e];
                    float d1 = c[mt][idx][2 * e + 1] - mu[mt][e];
                    sq = fmaf(d0, d0, sq);
                    sq = fmaf(d1, d1, sq);
                }
                sq += __shfl_xor_sync(0xffffffffu, sq, 1);
                sq += __shfl_xor_sync(0xffffffffu, sq, 2);
                if ((lane & 3) == 0) lnb[256 + row * 2 + nwarp] = sq;
            }
        __syncthreads();
#pragma unroll
        for (int mt = 0; mt < 2; mt++)
#pragma unroll
            for (int e = 0; e < 2; e++) {
                int row = mwarp * 32 + mt * 16 + (lane >> 2) + 8 * e;
                rs[mt][e] = rsqrtf((lnb[256 + row * 2] + lnb[256 + row * 2 + 1]) *
                                       (1.0f / 128.0f) + EPSV);
            }

#pragma unroll
        for (int mt = 0; mt < 2; mt++)
#pragma unroll
            for (int e = 0; e < 2; e++) {
                int row = mwarp * 32 + mt * 16 + (lane >> 2) + 8 * e;
                int gr = blockRow + row;
                if (gr >= nRows) continue;
                float m = mu[mt][e], q = rs[mt][e];
                if (MSG) {
                    const int drow = idxs[row];
                    float* op = aggF + (size_t)drow * LAT;
#pragma unroll
                    for (int idx = 0; idx < 8; idx++) {
                        int col = nwarp * 64 + (idx >> 1) * 16 + (idx & 1) * 8 + 2 * (lane & 3);
                        float v0 = (c[mt][idx][2 * e]     - m) * q * Gs[col]     + BEs[col];
                        float v1 = (c[mt][idx][2 * e + 1] - m) * q * Gs[col + 1] + BEs[col + 1];
                        red2(&op[col], v0, v1);
                    }
                } else {
#pragma unroll
                    for (int idx = 0; idx < 8; idx++) {
                        int col = nwarp * 64 + (idx >> 1) * 16 + (idx & 1) * 8 + 2 * (lane & 3);
                        float v0 = (c[mt][idx][2 * e]     - m) * q * Gs[col]     + BEs[col];
                        float v1 = (c[mt][idx][2 * e + 1] - m) * q * Gs[col + 1] + BEs[col + 1];
                        uint32_t rh = *(const uint32_t*)&resHi[(size_t)gr * LAT + col];
                        uint32_t rl = *(const uint32_t*)&resLo[(size_t)gr * LAT + col];
                        v0 += recon(rh, 0) + recon(rl, 0);
                        v1 += recon(rh, 1) + recon(rl, 1);
                        uint32_t hi, lo;
                        split_pair(v0, v1, hi, lo);
                        *(uint32_t*)&outHi[(size_t)gr * LAT + col] = hi;
                        *(uint32_t*)&outLo[(size_t)gr * LAT + col] = lo;
                        uint32_t off = (uint32_t)((col >> 6) * 16384) +
                                       swz((uint32_t)(row * 128 + (col & 63) * 2));
                        *(uint32_t*)(smp + E_H_HI + off) = hi;
                        *(uint32_t*)(smp + E_H_LO + off) = lo;
                    }
                }
            }
        __syncthreads();
    }

    if (doTail) {
        float c[2][8][4];
#pragma unroll
        for (int mt = 0; mt < 2; mt++)
#pragma unroll
            for (int i = 0; i < 8; i++)
#pragma unroll
                for (int j = 0; j < 4; j++) c[mt][i][j] = 0.f;

        for (int k2 = 0; k2 < 2; k2++) {
            CPA_WAIT(0);
            __syncthreads();
            const uint32_t abH = sb + E_H_HI + k2 * 16384;
            const uint32_t abL = sb + E_H_LO + k2 * 16384;
#pragma unroll
            for (int ks = 0; ks < 4; ks++) {
                const uint32_t kcA = (uint32_t)((ks * 2 + a_kx) * 16) ^ xm;
                const uint32_t kcB = (uint32_t)((ks * 2 + b_kx) * 16) ^ xm;
                uint32_t ah[2][4], al[2][4];
#pragma unroll
                for (int mt = 0; mt < 2; mt++) {
                    uint32_t ro = (uint32_t)((a_row0 + mt * 16) * 128);
                    ldsm4(abH + ro + kcA, ah[mt]);
                    ldsm4(abL + ro + kcA, al[mt]);
                }
#pragma unroll
                for (int g = 0; g < 4; g++) {
                    uint32_t bh[4], bl[4];
                    uint32_t ro = (uint32_t)((b_row0 + g * 16) * 128);
                    ldsm4(sb + E_W2 + ro + kcB, bh);
                    ldsm4(sb + E_W2 + 16384 + ro + kcB, bl);
#pragma unroll
                    for (int mt = 0; mt < 2; mt++)
#pragma unroll
                        for (int hf = 0; hf < 2; hf++) {
                            float* cc = c[mt][g * 2 + hf];
                            mma_bf16(cc, ah[mt], &bh[hf * 2]);
                            mma_bf16(cc, ah[mt], &bl[hf * 2]);
                            mma_bf16(cc, al[mt], &bh[hf * 2]);
                        }
                }
            }
            __syncthreads();
            if (k2 == 0) { fillW1c(1); CPA_COMMIT(); }
        }
#pragma unroll
        for (int mt = 0; mt < 2; mt++)
#pragma unroll
            for (int e = 0; e < 2; e++) {
                int row = mwarp * 32 + mt * 16 + (lane >> 2) + 8 * e;
                int gr = blockRow + row;
                if (gr >= nRows) continue;
#pragma unroll
                for (int idx = 0; idx < 8; idx++) {
                    int col = nwarp * 64 + (idx >> 1) * 16 + (idx & 1) * 8 + 2 * (lane & 3);
                    float2 o;
                    o.x = c[mt][idx][2 * e] + b1s[col];
                    o.y = c[mt][idx][2 * e + 1] + b1s[col + 1];
                    *(float2*)&Ye[(size_t)gr * 128 + col] = o;
                }
            }
    }
}

// ============================================================================
// encode_mlp: SIMT layer1 -> layer2 -> LN -> planes [+Ye tail]
// ============================================================================
#define N_H_HI 0
#define N_H_LO 32768
#define N_W2   65536
#define N_B1   98304
#define N_B2   98816
#define N_G    99328
#define N_BE   99840
#define N_LN   100352
#define N_W1R  102400
#define N_EB1  104448
#define SMEM_N 104960

__global__ __launch_bounds__(256, 2) void encode_mlp(
    const float* __restrict__ raw, const float* __restrict__ W1raw, int kreal,
    const float* __restrict__ B1,
    const __nv_bfloat16* __restrict__ W2hi, const __nv_bfloat16* __restrict__ W2lo,
    const float* __restrict__ B2,
    const float* __restrict__ G, const float* __restrict__ BE,
    const __nv_bfloat16* __restrict__ eW1hi, const __nv_bfloat16* __restrict__ eW1lo,
    const float* __restrict__ eB1, float* __restrict__ Ye, int doYe,
    __nv_bfloat16* __restrict__ outHi, __nv_bfloat16* __restrict__ outLo, int nRows)
{
    extern __shared__ char smp[];
    const uint32_t sb = smem_u32(smp);
    const int tid = threadIdx.x;
    const int wid = tid >> 5, lane = tid & 31;
    const int mwarp = wid & 3, nwarp = wid >> 2;
    const int blockRow = blockIdx.x * 128;

    float* b1s = (float*)(smp + N_B1);
    float* b2s = (float*)(smp + N_B2);
    float* Gs  = (float*)(smp + N_G);
    float* BEs = (float*)(smp + N_BE);
    float* lnb = (float*)(smp + N_LN);
    float* w1r = (float*)(smp + N_W1R);
    float* eb1 = (float*)(smp + N_EB1);

    if (tid < 128) {
        b1s[tid] = B1[tid]; b2s[tid] = B2[tid];
        Gs[tid] = G[tid];   BEs[tid] = BE[tid];
        if (doYe) eb1[tid] = eB1[tid];
    }
    for (int i = tid; i < kreal * 128; i += 256) w1r[i] = W1raw[i];
    __syncthreads();

    auto fillW2 = [&](int chunk) {
#pragma unroll
        for (int p = 0; p < 4; p++) {
            int idx = tid + 256 * p;
            int row = idx >> 3, qq = idx & 7;
            size_t go = (size_t)row * 128 + chunk * 64 + qq * 8;
            uint32_t sw = swz((uint32_t)(row * 128 + qq * 16));
            cpa16(sb + N_W2 + sw, W2hi + go);
            cpa16(sb + N_W2 + 16384 + sw, W2lo + go);
        }
    };
    auto fillW1c = [&](int chunk) {
#pragma unroll
        for (int p = 0; p < 4; p++) {
            int idx = tid + 256 * p;
            int row = idx >> 3, qq = idx & 7;
            size_t go = (size_t)row * 384 + 256 + chunk * 64 + qq * 8;
            uint32_t sw = swz((uint32_t)(row * 128 + qq * 16));
            cpa16(sb + N_W2 + sw, eW1hi + go);
            cpa16(sb + N_W2 + 16384 + sw, eW1lo + go);
        }
    };
    fillW2(0); CPA_COMMIT();

#pragma unroll 4
    for (int p = 0; p < 16; p++) {
        int idx = tid + 256 * p;
        int row = idx >> 5, qf = idx & 31;
        int col = qf * 4;
        int rc = min(blockRow + row, nRows - 1);
        float xv[4];
#pragma unroll
        for (int k = 0; k < 4; k++)
            xv[k] = (k < kreal) ? raw[(size_t)rc * kreal + k] : 0.f;
        float v[4];
#pragma unroll
        for (int j = 0; j < 4; j++) {
            float acc = b1s[col + j];
            for (int k = 0; k < kreal; k++)
                acc = fmaf(xv[k], w1r[k * 128 + col + j], acc);
            v[j] = fmaxf(acc, 0.f);
        }
        uint32_t h0, h1, l0, l1;
        split_pair(v[0], v[1], h0, l0);
        split_pair(v[2], v[3], h1, l1);
        uint32_t off = (uint32_t)((col >> 6) * 16384) +
                       swz((uint32_t)(row * 128 + (col & 63) * 2));
        *(uint2*)(smp + N_H_HI + off) = make_uint2(h0, h1);
        *(uint2*)(smp + N_H_LO + off) = make_uint2(l0, l1);
    }

    const int lrow = lane & 7, lg = lane >> 3;
    const uint32_t xm = (uint32_t)lrow << 4;
    const int a_row0 = mwarp * 32 + lrow + 8 * (lg & 1);
    const int a_kx = lg >> 1;
    const int b_row0 = nwarp * 64 + lrow + 8 * (lg >> 1);
    const int b_kx = lg & 1;

    float c[2][8][4];
#pragma unroll
    for (int mt = 0; mt < 2; mt++)
#pragma unroll
        for (int i = 0; i < 8; i++)
#pragma unroll
            for (int j = 0; j < 4; j++) c[mt][i][j] = 0.f;

    for (int c2 = 0; c2 < 2; c2++) {
        CPA_WAIT(0);
        __syncthreads();
        const uint32_t abH = sb + N_H_HI + c2 * 16384;
        const uint32_t abL = sb + N_H_LO + c2 * 16384;
#pragma unroll
        for (int ks = 0; ks < 4; ks++) {
            const uint32_t kcA = (uint32_t)((ks * 2 + a_kx) * 16) ^ xm;
            const uint32_t kcB = (uint32_t)((ks * 2 + b_kx) * 16) ^ xm;
            uint32_t ah[2][4], al[2][4];
#pragma unroll
            for (int mt = 0; mt < 2; mt++) {
                uint32_t ro = (uint32_t)((a_row0 + mt * 16) * 128);
                ldsm4(abH + ro + kcA, ah[mt]);
                ldsm4(abL + ro + kcA, al[mt]);
            }
#pragma unroll
            for (int g = 0; g < 4; g++) {
                uint32_t bh[4], bl[4];
                uint32_t ro = (uint32_t)((b_row0 + g * 16) * 128);
                ldsm4(sb + N_W2 + ro + kcB, bh);
                ldsm4(sb + N_W2 + 16384 + ro + kcB, bl);
#pragma unroll
                for (int mt = 0; mt < 2; mt++)
#pragma unroll
                    for (int hf = 0; hf < 2; hf++) {
                        float* cc = c[mt][g * 2 + hf];
                        mma_bf16(cc, ah[mt], &bh[hf * 2]);
                        mma_bf16(cc, ah[mt], &bl[hf * 2]);
                        mma_bf16(cc, al[mt], &bh[hf * 2]);
                    }
            }
        }
        __syncthreads();
        if (c2 == 0) { fillW2(1); CPA_COMMIT(); }
        else if (doYe) { fillW1c(0); CPA_COMMIT(); }
    }

#pragma unroll
    for (int mt = 0; mt < 2; mt++)
#pragma unroll
        for (int idx = 0; idx < 8; idx++) {
            int col = nwarp * 64 + (idx >> 1) * 16 + (idx & 1) * 8 + 2 * (lane & 3);
#pragma unroll
            for (int j = 0; j < 4; j++)
                c[mt][idx][j] = fmaxf(c[mt][idx][j] + b2s[col + (j & 1)], 0.f);
        }
#pragma unroll
    for (int mt = 0; mt < 2; mt++)
#pragma unroll
        for (int e = 0; e < 2; e++) {
            float s = 0.f;
#pragma unroll
            for (int idx = 0; idx < 8; idx++)
                s += c[mt][idx][2 * e] + c[mt][idx][2 * e + 1];
            s += __shfl_xor_sync(0xffffffffu, s, 1);
            s += __shfl_xor_sync(0xffffffffu, s, 2);
            if ((lane & 3) == 0) {
                int row = mwarp * 32 + mt * 16 + (lane >> 2) + 8 * e;
                lnb[row * 2 + nwarp] = s;
            }
        }
    __syncthreads();
    float mu[2][2], rs[2][2];
#pragma unroll
    for (int mt = 0; mt < 2; mt++)
#pragma unroll
        for (int e = 0; e < 2; e++) {
            int row = mwarp * 32 + mt * 16 + (lane >> 2) + 8 * e;
            mu[mt][e] = (lnb[row * 2] + lnb[row * 2 + 1]) * (1.0f / 128.0f);
            float sq = 0.f;
#pragma unroll
            for (int idx = 0; idx < 8; idx++) {
                float d0 = c[mt][idx][2 * e] - mu[mt][e];
                float d1 = c[mt][idx][2 * e + 1] - mu[mt][e];
                sq = fmaf(d0, d0, sq);
                sq = fmaf(d1, d1, sq);
            }
            sq += __shfl_xor_sync(0xffffffffu, sq, 1);
            sq += __shfl_xor_sync(0xffffffffu, sq, 2);
            if ((lane & 3) == 0) lnb[256 + row * 2 + nwarp] = sq;
        }
    __syncthreads();
#pragma unroll
    for (int mt = 0; mt < 2; mt++)
#pragma unroll
        for (int e = 0; e < 2; e++) {
            int row = mwarp * 32 + mt * 16 + (lane >> 2) + 8 * e;
            rs[mt][e] = rsqrtf((lnb[256 + row * 2] + lnb[256 + row * 2 + 1]) *
                                   (1.0f / 128.0f) + EPSV);
        }
#pragma unroll
    for (int mt = 0; mt < 2; mt++)
#pragma unroll
        for (int e = 0; e < 2; e++) {
            int row = mwarp * 32 + mt * 16 + (lane >> 2) + 8 * e;
            int gr = blockRow + row;
            if (gr >= nRows) continue;
            float m = mu[mt][e], q = rs[mt][e];
#pragma unroll
            for (int idx = 0; idx < 8; idx++) {
                int col = nwarp * 64 + (idx >> 1) * 16 + (idx & 1) * 8 + 2 * (lane & 3);
                float v0 = (c[mt][idx][2 * e]     - m) * q * Gs[col]     + BEs[col];
                float v1 = (c[mt][idx][2 * e + 1] - m) * q * Gs[col + 1] + BEs[col + 1];
                uint32_t hi, lo;
                split_pair(v0, v1, hi, lo);
                *(uint32_t*)&outHi[(size_t)gr * LAT + col] = hi;
                *(uint32_t*)&outLo[(size_t)gr * LAT + col] = lo;
                if (doYe) {
                    uint32_t off = (uint32_t)((col >> 6) * 16384) +
                                   swz((uint32_t)(row * 128 + (col & 63) * 2));
                    *(uint32_t*)(smp + N_H_HI + off) = hi;
                    *(uint32_t*)(smp + N_H_LO + off) = lo;
                }
            }
        }
    __syncthreads();

    if (doYe) {
#pragma unroll
        for (int mt = 0; mt < 2; mt++)
#pragma unroll
            for (int i = 0; i < 8; i++)
#pragma unroll
                for (int j = 0; j < 4; j++) c[mt][i][j] = 0.f;
        for (int k2 = 0; k2 < 2; k2++) {
            CPA_WAIT(0);
            __syncthreads();
            const uint32_t abH = sb + N_H_HI + k2 * 16384;
            const uint32_t abL = sb + N_H_LO + k2 * 16384;
#pragma unroll
            for (int ks = 0; ks < 4; ks++) {
                const uint32_t kcA = (uint32_t)((ks * 2 + a_kx) * 16) ^ xm;
                const uint32_t kcB = (uint32_t)((ks * 2 + b_kx) * 16) ^ xm;
                uint32_t ah[2][4], al[2][4];
#pragma unroll
                for (int mt = 0; mt < 2; mt++) {
                    uint32_t ro = (uint32_t)((a_row0 + mt * 16) * 128);
                    ldsm4(abH + ro + kcA, ah[mt]);
                    ldsm4(abL + ro + kcA, al[mt]);
                }
#pragma unroll
                for (int g = 0; g < 4; g++) {
                    uint32_t bh[4], bl[4];
                    uint32_t ro = (uint32_t)((b_row0 + g * 16) * 128);
                    ldsm4(sb + N_W2 + ro + kcB, bh);
                    ldsm4(sb + N_W2 + 16384 + ro + kcB, bl);
#pragma unroll
                    for (int mt = 0; mt < 2; mt++)
#pragma unroll
                        for (int hf = 0; hf < 2; hf++) {
                            float* cc = c[mt][g * 2 + hf];
                            mma_bf16(cc, ah[mt], &bh[hf * 2]);
                            mma_bf16(cc, ah[mt], &bl[hf * 2]);
                            mma_bf16(cc, al[mt], &bh[hf * 2]);
                        }
                }
            }
            __syncthreads();
            if (k2 == 0) { fillW1c(1); CPA_COMMIT(); }
        }
#pragma unroll
        for (int mt = 0; mt < 2; mt++)
#pragma unroll
            for (int e = 0; e < 2; e++) {
                int row = mwarp * 32 + mt * 16 + (lane >> 2) + 8 * e;
                int gr = blockRow + row;
                if (gr >= nRows) continue;
#pragma unroll
                for (int idx = 0; idx < 8; idx++) {
                    int col = nwarp * 64 + (idx >> 1) * 16 + (idx & 1) * 8 + 2 * (lane & 3);
                    float2 o;
                    o.x = c[mt][idx][2 * e] + eb1[col];
                    o.y = c[mt][idx][2 * e + 1] + eb1[col + 1];
                    *(float2*)&Ye[(size_t)gr * 128 + col] = o;
                }
            }
    }
}

// ============================================================================
// node_update v2: 2 CTAs/SM; A just-in-time 2x32KB ping-pong (reused as H);
// W1/W2 streamed through one 32KB buffer. Zeroes agg rows (doZero).
// ============================================================================
#define U_BUF(b)  ((b) * 32768)
#define U_H_HI    0
#define U_H_LO    32768
#define U_W       65536
#define U_B1      98304
#define U_B2      98816
#define U_G       99328
#define U_BE      99840
#define U_LN      100352
#define SMEM_U    102400

__global__ __launch_bounds__(256, 2) void node_update(
    float* __restrict__ aggF,
    const __nv_bfloat16* __restrict__ hHi, const __nv_bfloat16* __restrict__ hLo,
    const __nv_bfloat16* __restrict__ W1hi, const __nv_bfloat16* __restrict__ W1lo,
    const float* __restrict__ B1,
    const __nv_bfloat16* __restrict__ W2hi, const __nv_bfloat16* __restrict__ W2lo,
    const float* __restrict__ B2,
    const float* __restrict__ G, const float* __restrict__ BE,
    const __nv_bfloat16* __restrict__ resHi, const __nv_bfloat16* __restrict__ resLo,
    __nv_bfloat16* __restrict__ outHi, __nv_bfloat16* __restrict__ outLo,
    int doZero, int nRows)
{
    extern __shared__ char smp[];
    const uint32_t sb = smem_u32(smp);
    const int tid = threadIdx.x;
    const int wid = tid >> 5, lane = tid & 31;
    const int mwarp = wid & 3, nwarp = wid >> 2;
    const int blockRow = blockIdx.x * 128;

    float* b1s = (float*)(smp + U_B1);
    float* b2s = (float*)(smp + U_B2);
    float* Gs  = (float*)(smp + U_G);
    float* BEs = (float*)(smp + U_BE);
    float* lnb = (float*)(smp + U_LN);

    if (tid < 128) {
        b1s[tid] = B1[tid]; b2s[tid] = B2[tid];
        Gs[tid] = G[tid];   BEs[tid] = BE[tid];
    }
    __syncthreads();

    auto fillW1 = [&](int ch) {
#pragma unroll
        for (int p = 0; p < 4; p++) {
            int idx = tid + 256 * p;
            int row = idx >> 3, qq = idx & 7;
            size_t go = (size_t)row * 256 + ch * 64 + qq * 8;
            uint32_t sw = swz((uint32_t)(row * 128 + qq * 16));
            cpa16(sb + U_W + sw, W1hi + go);
            cpa16(sb + U_W + 16384 + sw, W1lo + go);
        }
    };
    auto fillW2c = [&](int ch) {
#pragma unroll
        for (int p = 0; p < 4; p++) {
            int idx = tid + 256 * p;
            int row = idx >> 3, qq = idx & 7;
            size_t go = (size_t)row * 128 + ch * 64 + qq * 8;
            uint32_t sw = swz((uint32_t)(row * 128 + qq * 16));
            cpa16(sb + U_W + sw, W2hi + go);
            cpa16(sb + U_W + 16384 + sw, W2lo + go);
        }
    };
    auto fillA = [&](int ch) {
        const uint32_t bbase = sb + U_BUF(ch & 1);
        char* bptr = smp + U_BUF(ch & 1);
        if (ch < 2) {
            const int koff = ch * 64;
#pragma unroll
            for (int p = 0; p < 8; p++) {
                int idx = tid + 256 * p;
                int row = idx >> 4, f4 = idx & 15;
                int ri = min(blockRow + row, nRows - 1);
                float4 v = *(const float4*)&aggF[(size_t)ri * LAT + koff + f4 * 4];
                uint32_t h0, h1, l0, l1;
                split_pair(v.x, v.y, h0, l0);
                split_pair(v.z, v.w, h1, l1);
                uint32_t sw = swz((uint32_t)(row * 128 + f4 * 8));
                *(uint2*)(bptr + sw) = make_uint2(h0, h1);
                *(uint2*)(bptr + 16384 + sw) = make_uint2(l0, l1);
            }
        } else {
            const int koff = (ch - 2) * 64;
#pragma unroll
            for (int p = 0; p < 4; p++) {
                int idx = tid + 256 * p;
                int row = idx >> 3, q = idx & 7;
                int ri = min(blockRow + row, nRows - 1);
                size_t go = (size_t)ri * LAT + koff + q * 8;
                uint32_t sw = swz((uint32_t)(row * 128 + q * 16));
                cpa16(bbase + sw, hHi + go);
                cpa16(bbase + 16384 + sw, hLo + go);
            }
        }
    };

    const int lrow = lane & 7, lg = lane >> 3;
    const uint32_t xm = (uint32_t)lrow << 4;
    const int a_row0 = mwarp * 32 + lrow + 8 * (lg & 1);
    const int a_kx = lg >> 1;
    const int b_row0 = nwarp * 64 + lrow + 8 * (lg >> 1);
    const int b_kx = lg & 1;

    float c[2][8][4];
#pragma unroll
    for (int mt = 0; mt < 2; mt++)
#pragma unroll
        for (int i = 0; i < 8; i++)
#pragma unroll
            for (int j = 0; j < 4; j++) c[mt][i][j] = 0.f;

    fillW1(0); CPA_COMMIT();

    for (int ch = 0; ch < 4; ch++) {
        fillA(ch);
        if (ch >= 2) CPA_COMMIT();
        CPA_WAIT(0);
        __syncthreads();
        if (ch == 1 && doZero) {
#pragma unroll
            for (int p = 0; p < 16; p++) {
                int idx = tid + 256 * p;
                int row = idx >> 5, f4 = idx & 31;
                int gr = blockRow + row;
                if (gr < nRows)
                    *(float4*)&aggF[(size_t)gr * LAT + f4 * 4] =
                        make_float4(0.f, 0.f, 0.f, 0.f);
            }
        }
        const uint32_t ab = sb + U_BUF(ch & 1);
#pragma unroll
        for (int ks = 0; ks < 4; ks++) {
            const uint32_t kcA = (uint32_t)((ks * 2 + a_kx) * 16) ^ xm;
            const uint32_t kcB = (uint32_t)((ks * 2 + b_kx) * 16) ^ xm;
            uint32_t ah[2][4], al[2][4];
#pragma unroll
            for (int mt = 0; mt < 2; mt++) {
                uint32_t ro = (uint32_t)((a_row0 + mt * 16) * 128);
                ldsm4(ab + ro + kcA, ah[mt]);
                ldsm4(ab + 16384 + ro + kcA, al[mt]);
            }
#pragma unroll
            for (int g = 0; g < 4; g++) {
                uint32_t bh[4], bl[4];
                uint32_t ro = (uint32_t)((b_row0 + g * 16) * 128);
                ldsm4(sb + U_W + ro + kcB, bh);
                ldsm4(sb + U_W + 16384 + ro + kcB, bl);
#pragma unroll
                for (int mt = 0; mt < 2; mt++)
#pragma unroll
                    for (int hf = 0; hf < 2; hf++) {
                        float* cc = c[mt][g * 2 + hf];
                        mma_bf16(cc, ah[mt], &bh[hf * 2]);
                        mma_bf16(cc, ah[mt], &bl[hf * 2]);
                        mma_bf16(cc, al[mt], &bh[hf * 2]);
                    }
            }
        }
        __syncthreads();
        if (ch < 3) { fillW1(ch + 1); CPA_COMMIT(); }
        else        { fillW2c(0);     CPA_COMMIT(); }
    }

#pragma unroll
    for (int mt = 0; mt < 2; mt++)
#pragma unroll
        for (int idx = 0; idx < 8; idx++)
#pragma unroll
            for (int e = 0; e < 2; e++) {
                int row = mwarp * 32 + mt * 16 + (lane >> 2) + 8 * e;
                int col = nwarp * 64 + (idx >> 1) * 16 + (idx & 1) * 8 + 2 * (lane & 3);
                float v0 = fmaxf(c[mt][idx][2 * e] + b1s[col], 0.f);
                float v1 = fmaxf(c[mt][idx][2 * e + 1] + b1s[col + 1], 0.f);
                uint32_t hi, lo;
                split_pair(v0, v1, hi, lo);
                uint32_t off = (uint32_t)(nwarp * 16384 + row * 128 +
                                          (((col & 63) * 2) ^ ((row & 7) << 4)));
                *(uint32_t*)(smp + U_H_HI + off) = hi;
                *(uint32_t*)(smp + U_H_LO + off) = lo;
            }
#pragma unroll
    for (int mt = 0; mt < 2; mt++)
#pragma unroll
        for (int i = 0; i < 8; i++)
#pragma unroll
            for (int j = 0; j < 4; j++) c[mt][i][j] = 0.f;

    for (int c2 = 0; c2 < 2; c2++) {
        CPA_WAIT(0);
        __syncthreads();
        const uint32_t abH = sb + U_H_HI + c2 * 16384;
        const uint32_t abL = sb + U_H_LO + c2 * 16384;
#pragma unroll
        for (int ks = 0; ks < 4; ks++) {
            const uint32_t kcA = (uint32_t)((ks * 2 + a_kx) * 16) ^ xm;
            const uint32_t kcB = (uint32_t)((ks * 2 + b_kx) * 16) ^ xm;
            uint32_t ah[2][4], al[2][4];
#pragma unroll
            for (int mt = 0; mt < 2; mt++) {
                uint32_t ro = (uint32_t)((a_row0 + mt * 16) * 128);
                ldsm4(abH + ro + kcA, ah[mt]);
                ldsm4(abL + ro + kcA, al[mt]);
            }
#pragma unroll
            for (int g = 0; g < 4; g++) {
                uint32_t bh[4], bl[4];
                uint32_t ro = (uint32_t)((b_row0 + g * 16) * 128);
                ldsm4(sb + U_W + ro + kcB, bh);
                ldsm4(sb + U_W + 16384 + ro + kcB, bl);
#pragma unroll
                for (int mt = 0; mt < 2; mt++)
#pragma unroll
                    for (int hf = 0; hf < 2; hf++) {
                        float* cc = c[mt][g * 2 + hf];
                        mma_bf16(cc, ah[mt], &bh[hf * 2]);
                        mma_bf16(cc, ah[mt], &bl[hf * 2]);
                        mma_bf16(cc, al[mt], &bh[hf * 2]);
                    }
            }
        }
        __syncthreads();
        if (c2 == 0) { fillW2c(1); CPA_COMMIT(); }
    }

#pragma unroll
    for (int mt = 0; mt < 2; mt++)
#pragma unroll
        for (int idx = 0; idx < 8; idx++) {
            int col = nwarp * 64 + (idx >> 1) * 16 + (idx & 1) * 8 + 2 * (lane & 3);
#pragma unroll
            for (int j = 0; j < 4; j++)
                c[mt][idx][j] = fmaxf(c[mt][idx][j] + b2s[col + (j & 1)], 0.f);
        }

#pragma unroll
    for (int mt = 0; mt < 2; mt++)
#pragma unroll
        for (int e = 0; e < 2; e++) {
            float s = 0.f;
#pragma unroll
            for (int idx = 0; idx < 8; idx++)
                s += c[mt][idx][2 * e] + c[mt][idx][2 * e + 1];
            s += __shfl_xor_sync(0xffffffffu, s, 1);
            s += __shfl_xor_sync(0xffffffffu, s, 2);
            if ((lane & 3) == 0) {
                int row = mwarp * 32 + mt * 16 + (lane >> 2) + 8 * e;
                lnb[row * 2 + nwarp] = s;
            }
        }
    __syncthreads();
    float mu[2][2], rs[2][2];
#pragma unroll
    for (int mt = 0; mt < 2; mt++)
#pragma unroll
        for (int e = 0; e < 2; e++) {
            int row = mwarp * 32 + mt * 16 + (lane >> 2) + 8 * e;
            mu[mt][e] = (lnb[row * 2] + lnb[row * 2 + 1]) * (1.0f / 128.0f);
            float sq = 0.f;
#pragma unroll
            for (int idx = 0; idx < 8; idx++) {
                float d0 = c[mt][idx][2 * e] - mu[mt][e];
                float d1 = c[mt][idx][2 * e + 1] - mu[mt][e];
                sq = fmaf(d0, d0, sq);
                sq = fmaf(d1, d1, sq);
            }
            sq += __shfl_xor_sync(0xffffffffu, sq, 1);
            sq += __shfl_xor_sync(0xffffffffu, sq, 2);
            if ((lane & 3) == 0) lnb[256 + row * 2 + nwarp] = sq;
        }
    __syncthreads();
#pragma unroll
    for (int mt = 0; mt < 2; mt++)
#pragma unroll
        for (int e = 0; e < 2; e++) {
            int row = mwarp * 32 + mt * 16 + (lane >> 2) + 8 * e;
            rs[mt][e] = rsqrtf((lnb[256 + row * 2] + lnb[256 + row * 2 + 1]) *
                                   (1.0f / 128.0f) + EPSV);
        }

#pragma unroll
    for (int mt = 0; mt < 2; mt++)
#pragma unroll
        for (int e = 0; e < 2; e++) {
            int row = mwarp * 32 + mt * 16 + (lane >> 2) + 8 * e;
            int gr = blockRow + row;
            if (gr >= nRows) continue;
            float m = mu[mt][e], q = rs[mt][e];
#pragma unroll
            for (int idx = 0; idx < 8; idx++) {
                int col = nwarp * 64 + (idx >> 1) * 16 + (idx & 1) * 8 + 2 * (lane & 3);
                float v0 = (c[mt][idx][2 * e]     - m) * q * Gs[col]     + BEs[col];
                float v1 = (c[mt][idx][2 * e + 1] - m) * q * Gs[col + 1] + BEs[col + 1];
                uint32_t rh = *(const uint32_t*)&resHi[(size_t)gr * LAT + col];
                uint32_t rl = *(const uint32_t*)&resLo[(size_t)gr * LAT + col];
                v0 += recon(rh, 0) + recon(rl, 0);
                v1 += recon(rh, 1) + recon(rl, 1);
                uint32_t hi, lo;
                split_pair(v0, v1, hi, lo);
                *(uint32_t*)&outHi[(size_t)gr * LAT + col] = hi;
                *(uint32_t*)&outLo[(size_t)gr * LAT + col] = lo;
            }
        }
}

__global__ void prep_all(
    const float* __restrict__ s0, __nv_bfloat16* __restrict__ h0b, __nv_bfloat16* __restrict__ l0b,
    const float* __restrict__ s1, __nv_bfloat16* __restrict__ h1b, __nv_bfloat16* __restrict__ l1b,
    const float* __restrict__ s2, __nv_bfloat16* __restrict__ h2b, __nv_bfloat16* __restrict__ l2b,
    const float* __restrict__ s3, __nv_bfloat16* __restrict__ h3b, __nv_bfloat16* __restrict__ l3b,
    const float* __restrict__ s4, __nv_bfloat16* __restrict__ h4b, __nv_bfloat16* __restrict__ l4b,
    const float* __restrict__ s5, __nv_bfloat16* __restrict__ h5b, __nv_bfloat16* __restrict__ l5b)
{
    int i = blockIdx.x * blockDim.x + threadIdx.x;
    const float* W; __nv_bfloat16 *hi, *lo; int K, j;
    if (i < 49152)       { W = s0; hi = h0b; lo = l0b; K = 384; j = i; }
    else if (i < 65536)  { W = s1; hi = h1b; lo = l1b; K = 128; j = i - 49152; }
    else if (i < 98304)  { W = s2; hi = h2b; lo = l2b; K = 256; j = i - 65536; }
    else if (i < 114688) { W = s3; hi = h3b; lo = l3b; K = 128; j = i - 98304; }
    else if (i < 131072) { W = s4; hi = h4b; lo = l4b; K = 128; j = i - 114688; }
    else if (i < 147456) { W = s5; hi = h5b; lo = l5b; K = 128; j = i - 131072; }
    else return;
    int k = j >> 7, n = j & 127;
    float v = W[j];
    __nv_bfloat16 h = __float2bfloat16(v);
    hi[(size_t)n * K + k] = h;
    lo[(size_t)n * K + k] = __float2bfloat16(v - __bfloat162float(h));
}

__global__ __launch_bounds__(256) void decoder_kernel(
    const __nv_bfloat16* __restrict__ hHi, const __nv_bfloat16* __restrict__ hLo,
    const float* __restrict__ W1, const float* __restrict__ B1,
    const float* __restrict__ W2, const float* __restrict__ B2,
    float* __restrict__ out, int n)
{
    extern __shared__ float s[];
    float* W1s = s;
    float* hs = s + 128 * 128;
    int tid = threadIdx.x;
#pragma unroll
    for (int it = 0; it < 16; it++) {
        int f = tid + 256 * it;
        *(float4*)&W1s[f * 4] = *(const float4*)&W1[f * 4];
    }
    int warp = tid >> 5, lane = tid & 31;
    int row = blockIdx.x * 8 + warp;
    int rc = min(row, n - 1);
#pragma unroll
    for (int q = 0; q < 4; q++) {
        int cc = lane + 32 * q;
        hs[warp * 128 + cc] = __bfloat162float(hHi[(size_t)rc * LAT + cc]) +
                              __bfloat162float(hLo[(size_t)rc * LAT + cc]);
    }
    __syncthreads();

    float acc[4];
#pragma unroll
    for (int q = 0; q < 4; q++) acc[q] = B1[lane + 32 * q];
    for (int k = 0; k < 128; k++) {
        float hv = hs[warp * 128 + k];
#pragma unroll
        for (int q = 0; q < 4; q++)
            acc[q] = fmaf(hv, W1s[k * 128 + lane + 32 * q], acc[q]);
    }
#pragma unroll
    for (int q = 0; q < 4; q++) acc[q] = fmaxf(acc[q], 0.f);

    float o[3];
#pragma unroll
    for (int oo = 0; oo < 3; oo++) {
        float p = 0.f;
#pragma unroll
        for (int q = 0; q < 4; q++)
            p = fmaf(acc[q], W2[(size_t)(lane + 32 * q) * 3 + oo], p);
#pragma unroll
        for (int off = 16; off > 0; off >>= 1)
            p += __shfl_xor_sync(0xffffffffu, p, off);
        o[oo] = p;
    }
    if (lane == 0 && row < n) {
        out[(size_t)row * 3 + 0] = o[0] + B2[0];
        out[(size_t)row * 3 + 1] = o[1] + B2[1];
        out[(size_t)row * 3 + 2] = o[2] + B2[2];
    }
}

__global__ void zero_kernel(float4* __restrict__ p, int n4)
{
    int i = blockIdx.x * blockDim.x + threadIdx.x;
    if (i < n4) p[i] = make_float4(0.f, 0.f, 0.f, 0.f);
}

extern "C" void kernel_launch(void* const* d_in, const int* in_sizes, int n_in,
                              void* d_out, int out_size)
{
    (void)in_sizes; (void)n_in; (void)out_size;
    const float* x  = (const float*)d_in[0];
    const float* ea = (const float*)d_in[1];
    const int*   ei = (const int*)d_in[2];
    const int* src = ei;
    const int* dst = ei + NEDGES;

    const float* ne_w1 = (const float*)d_in[3];
    const float* ne_b1 = (const float*)d_in[4];
    const float* ne_w2 = (const float*)d_in[5];
    const float* ne_b2 = (const float*)d_in[6];
    const float* ne_g  = (const float*)d_in[7];
    const float* ne_be = (const float*)d_in[8];
    const float* ee_w1 = (const float*)d_in[9];
    const float* ee_b1 = (const float*)d_in[10];
    const float* ee_w2 = (const float*)d_in[11];
    const float* ee_b2 = (const float*)d_in[12];
    const float* ee_g  = (const float*)d_in[13];
    const float* ee_be = (const float*)d_in[14];
    const float* em_w1 = (const float*)d_in[15];
    const float* em_b1 = (const float*)d_in[16];
    const float* em_w2 = (const float*)d_in[17];
    const float* em_b2 = (const float*)d_in[18];
    const float* em_g  = (const float*)d_in[19];
    const float* em_be = (const float*)d_in[20];
    const float* nm_w1 = (const float*)d_in[21];
    const float* nm_b1 = (const float*)d_in[22];
    const float* nm_w2 = (const float*)d_in[23];
    const float* nm_b2 = (const float*)d_in[24];
    const float* nm_g  = (const float*)d_in[25];
    const float* nm_be = (const float*)d_in[26];
    const float* dw1   = (const float*)d_in[27];
    const float* db1   = (const float*)d_in[28];
    const float* dw2   = (const float*)d_in[29];
    const float* db2   = (const float*)d_in[30];

    float* fb = nullptr;
    cudaGetSymbolAddress((void**)&fb, g_fbuf);
    float* agg = fb;
    float* Y12 = fb + (size_t)NNODES * LAT;
    float* Ye  = fb + (size_t)3 * NNODES * LAT;

    __nv_bfloat16* hp = nullptr;
    cudaGetSymbolAddress((void**)&hp, g_hpl);
    __nv_bfloat16* ep = nullptr;
    cudaGetSymbolAddress((void**)&ep, g_epl);
    const size_t HS = (size_t)NNODES * LAT, ES = (size_t)NEDGES * LAT;
    __nv_bfloat16 *hH0 = hp, *hL0 = hp + HS, *hH1 = hp + 2 * HS, *hL1 = hp + 3 * HS;
    __nv_bfloat16 *eH0 = ep, *eL0 = ep + ES, *eH1 = ep + 2 * ES, *eL1 = ep + 3 * ES;

    __nv_bfloat16* pl = nullptr;
    cudaGetSymbolAddress((void**)&pl, g_planes);
    __nv_bfloat16* emW1h = pl;
    __nv_bfloat16* emW1l = pl + 49152;
    __nv_bfloat16* emW2h = pl + 98304;
    __nv_bfloat16* emW2l = pl + 114688;
    __nv_bfloat16* nmW1h = pl + 131072;
    __nv_bfloat16* nmW1l = pl + 163840;
    __nv_bfloat16* nmW2h = pl + 196608;
    __nv_bfloat16* nmW2l = pl + 212992;
    __nv_bfloat16* neW2h = pl + 229376;
    __nv_bfloat16* neW2l = pl + 245760;
    __nv_bfloat16* eeW2h = pl + 262144;
    __nv_bfloat16* eeW2l = pl + 278528;

    cudaFuncSetAttribute(node_update,
                         cudaFuncAttributeMaxDynamicSharedMemorySize, SMEM_U);
    cudaFuncSetAttribute(edge_fused,
                         cudaFuncAttributeMaxDynamicSharedMemorySize, SMEM_E);
    cudaFuncSetAttribute(gemm_y12,
                         cudaFuncAttributeMaxDynamicSharedMemorySize, SMEM_Y);
    cudaFuncSetAttribute(encode_mlp,
                         cudaFuncAttributeMaxDynamicSharedMemorySize, SMEM_N);
    const int DSM = (128 * 128 + 8 * 128) * (int)sizeof(float);
    cudaFuncSetAttribute(decoder_kernel,
                         cudaFuncAttributeMaxDynamicSharedMemorySize, DSM);

    prep_all<<<(147456 + 255) / 256, 256>>>(
        em_w1, emW1h, emW1l, em_w2, emW2h, emW2l,
        nm_w1, nmW1h, nmW1l, nm_w2, nmW2h, nmW2l,
        ne_w2, neW2h, neW2l, ee_w2, eeW2h, eeW2l);

    dim3 blk(256);
    const int ntiles = (NNODES + 127) / 128;  // 391
    const int etiles = NEDGES / 128;          // 3125

    encode_mlp<<<ntiles, blk, SMEM_N>>>(
        x, ne_w1, 3, ne_b1, neW2h, neW2l, ne_b2, ne_g, ne_be,
        nullptr, nullptr, nullptr, nullptr, 0, hH0, hL0, NNODES);
    encode_mlp<<<etiles, blk, SMEM_N>>>(
        ea, ee_w1, 4, ee_b1, eeW2h, eeW2l, ee_b2, ee_g, ee_be,
        emW1h, emW1l, em_b1, Ye, 1, eH0, eL0, NEDGES);
    zero_kernel<<<(NNODES * LAT / 4 + 255) / 256, 256>>>((float4*)agg,
                                                         NNODES * LAT / 4);

    __nv_bfloat16 *hcH = hH0, *hcL = hL0, *hnH = hH1, *hnL = hL1;
    __nv_bfloat16 *ecH = eH0, *ecL = eL0, *enH = eH1, *enL = eL1;
    for (int s = 0; s < 5; s++) {
        gemm_y12<<<ntiles, blk, SMEM_Y>>>(hcH, hcL, emW1h, emW1l, Y12, NNODES);
        edge_fused<<<etiles, blk, SMEM_E>>>(
            Y12, Ye, dst, src, emW2h, emW2l, em_b2, em_g, em_be,
            emW1h, emW1l, em_b1,
            ecH, ecL, enH, enL, agg, (s < 4) ? 1 : 0, NEDGES);
        node_update<<<ntiles, blk, SMEM_U>>>(
            agg, hcH, hcL, nmW1h, nmW1l, nm_b1, nmW2h, nmW2l, nm_b2, nm_g, nm_be,
            hcH, hcL, hnH, hnL, (s < 4) ? 1 : 0, NNODES);
        __nv_bfloat16* t;
        t = hcH; hcH = hnH; hnH = t;
        t = hcL; hcL = hnL; hnL = t;
        t = ecH; ecH = enH; enH = t;
        t = ecL; ecL = enL; enL = t;
    }

    decoder_kernel<<<(NNODES + 7) / 8, blk, DSM>>>(
        hcH, hcL, dw1, db1, dw2, db2, (float*)d_out, NNODES);
}